// round 1
// baseline (speedup 1.0000x reference)
#include <cuda_runtime.h>

// Problem constants
#define Nn   4
#define Cc   512
#define Ss   2048
#define Hh   8
#define CH   4096    // C*H
#define KV2  8192    // C*H*2
#define CTXD 512

#define SCALE2 0.044194173824159216f   // 512^-0.5

// Scratch (device globals — allocation-free rule)
__device__ float g_q  [(size_t)Nn * CH  * Ss];   // 128 MB
__device__ float g_kv [(size_t)Nn * KV2 * Ss];   // 256 MB
__device__ float g_att[(size_t)Nn * Hh * Ss * Ss]; // 512 MB
__device__ float g_y  [(size_t)Nn * CH  * Ss];   // 128 MB
__device__ float g_part[Nn * 128 * 2];
__device__ float g_stats[Nn * 2];                // mu, rsigma per sample

// ---------------------------------------------------------------------------
// LayerNorm statistics: stage 1 partial sums, stage 2 finalize
// ---------------------------------------------------------------------------
__global__ void ln_part_kernel(const float* __restrict__ x) {
    int n = blockIdx.y;
    int b = blockIdx.x;                       // 0..127
    const int chunk = (Cc * Ss) / 128;        // 8192 floats
    const float4* p4 = (const float4*)(x + (size_t)n * Cc * Ss + (size_t)b * chunk);
    float s = 0.f, s2 = 0.f;
    for (int i = threadIdx.x; i < chunk / 4; i += 256) {
        float4 v = p4[i];
        s  += v.x + v.y + v.z + v.w;
        s2 += v.x * v.x + v.y * v.y + v.z * v.z + v.w * v.w;
    }
    __shared__ float sh0[256], sh1[256];
    sh0[threadIdx.x] = s; sh1[threadIdx.x] = s2;
    __syncthreads();
    for (int o = 128; o > 0; o >>= 1) {
        if (threadIdx.x < o) {
            sh0[threadIdx.x] += sh0[threadIdx.x + o];
            sh1[threadIdx.x] += sh1[threadIdx.x + o];
        }
        __syncthreads();
    }
    if (threadIdx.x == 0) {
        g_part[(n * 128 + b) * 2 + 0] = sh0[0];
        g_part[(n * 128 + b) * 2 + 1] = sh1[0];
    }
}

__global__ void ln_fin_kernel() {
    int n = blockIdx.x;
    int t = threadIdx.x;  // 128 threads
    float s  = g_part[(n * 128 + t) * 2 + 0];
    float s2 = g_part[(n * 128 + t) * 2 + 1];
    __shared__ float sh0[128], sh1[128];
    sh0[t] = s; sh1[t] = s2;
    __syncthreads();
    for (int o = 64; o > 0; o >>= 1) {
        if (t < o) { sh0[t] += sh0[t + o]; sh1[t] += sh1[t + o]; }
        __syncthreads();
    }
    if (t == 0) {
        const float inv = 1.0f / (float)(Cc * Ss);
        float mu  = sh0[0] * inv;
        float var = sh1[0] * inv - mu * mu;
        g_stats[n * 2 + 0] = mu;
        g_stats[n * 2 + 1] = rsqrtf(var + 1e-5f);
    }
}

// ---------------------------------------------------------------------------
// Shared 64x64x16 tile compute (256 threads, 4x4 per thread)
// ---------------------------------------------------------------------------
__device__ __forceinline__ void mm_tile(const float (*As)[68], const float (*Bs)[68],
                                        float acc[4][4], int tx, int ty) {
#pragma unroll
    for (int kk = 0; kk < 16; kk++) {
        float4 a = *(const float4*)&As[kk][ty * 4];
        float4 b = *(const float4*)&Bs[kk][tx * 4];
        float av[4] = {a.x, a.y, a.z, a.w};
        float bv[4] = {b.x, b.y, b.z, b.w};
#pragma unroll
        for (int i = 0; i < 4; i++)
#pragma unroll
            for (int j = 0; j < 4; j++)
                acc[i][j] += av[i] * bv[j];
    }
}

// ---------------------------------------------------------------------------
// GEMM 1: q = Wq @ LN(input) + bq    (per n: [4096x512] @ [512x2048])
// LN applied on the fly to the B operand.
// ---------------------------------------------------------------------------
__global__ __launch_bounds__(256) void gemm_q_kernel(
    const float* __restrict__ Wq, const float* __restrict__ bq,
    const float* __restrict__ input,
    const float* __restrict__ gamma, const float* __restrict__ beta)
{
    int n  = blockIdx.z;
    int m0 = blockIdx.y * 64;
    int j0 = blockIdx.x * 64;
    float mu = g_stats[n * 2 + 0], rs = g_stats[n * 2 + 1];
    const float* B = input + (size_t)n * Cc * Ss;

    __shared__ float As[16][68], Bs[16][68];
    float acc[4][4] = {};
    int tid = threadIdx.x;
    int tx = tid & 15, ty = tid >> 4;
    int ac = (tid & 3) * 4, ar = tid >> 2;   // A loader (transpose)
    int bj = (tid & 15) * 4, bk = tid >> 4;  // B loader (direct)

    for (int k0 = 0; k0 < Cc; k0 += 16) {
        float4 a4 = *(const float4*)&Wq[(size_t)(m0 + ar) * Cc + k0 + ac];
        As[ac + 0][ar] = a4.x; As[ac + 1][ar] = a4.y;
        As[ac + 2][ar] = a4.z; As[ac + 3][ar] = a4.w;

        int c = k0 + bk;
        float4 b4 = *(const float4*)&B[(size_t)c * Ss + j0 + bj];
        float g  = gamma[c] * rs;
        float bb = beta[c] - mu * g;
        b4.x = b4.x * g + bb; b4.y = b4.y * g + bb;
        b4.z = b4.z * g + bb; b4.w = b4.w * g + bb;
        *(float4*)&Bs[bk][bj] = b4;
        __syncthreads();
        mm_tile(As, Bs, acc, tx, ty);
        __syncthreads();
    }
    float* Cp = g_q + (size_t)n * CH * Ss;
#pragma unroll
    for (int i = 0; i < 4; i++) {
        int m = m0 + ty * 4 + i;
        float bqi = bq[m];
        float4 o = {acc[i][0] + bqi, acc[i][1] + bqi, acc[i][2] + bqi, acc[i][3] + bqi};
        *(float4*)&Cp[(size_t)m * Ss + j0 + tx * 4] = o;
    }
}

// ---------------------------------------------------------------------------
// GEMM 2: kv = Wkv @ context + bkv   (per n: [8192x512] @ [512x2048])
// ---------------------------------------------------------------------------
__global__ __launch_bounds__(256) void gemm_kv_kernel(
    const float* __restrict__ Wkv, const float* __restrict__ bkv,
    const float* __restrict__ context)
{
    int n  = blockIdx.z;
    int m0 = blockIdx.y * 64;
    int j0 = blockIdx.x * 64;
    const float* B = context + (size_t)n * CTXD * Ss;

    __shared__ float As[16][68], Bs[16][68];
    float acc[4][4] = {};
    int tid = threadIdx.x;
    int tx = tid & 15, ty = tid >> 4;
    int ac = (tid & 3) * 4, ar = tid >> 2;
    int bj = (tid & 15) * 4, bk = tid >> 4;

    for (int k0 = 0; k0 < CTXD; k0 += 16) {
        float4 a4 = *(const float4*)&Wkv[(size_t)(m0 + ar) * CTXD + k0 + ac];
        As[ac + 0][ar] = a4.x; As[ac + 1][ar] = a4.y;
        As[ac + 2][ar] = a4.z; As[ac + 3][ar] = a4.w;
        float4 b4 = *(const float4*)&B[(size_t)(k0 + bk) * Ss + j0 + bj];
        *(float4*)&Bs[bk][bj] = b4;
        __syncthreads();
        mm_tile(As, Bs, acc, tx, ty);
        __syncthreads();
    }
    float* Cp = g_kv + (size_t)n * KV2 * Ss;
#pragma unroll
    for (int i = 0; i < 4; i++) {
        int m = m0 + ty * 4 + i;
        float bi = bkv[m];
        float4 o = {acc[i][0] + bi, acc[i][1] + bi, acc[i][2] + bi, acc[i][3] + bi};
        *(float4*)&Cp[(size_t)m * Ss + j0 + tx * 4] = o;
    }
}

// ---------------------------------------------------------------------------
// GEMM 3: scores[qs,ks] = (1/sqrt(C)) * sum_c q[c,qs] * k[c,ks]   (A^T B)
// ---------------------------------------------------------------------------
__global__ __launch_bounds__(256) void gemm_scores_kernel() {
    int z = blockIdx.z;            // n*8 + h
    int n = z >> 3, h = z & 7;
    const float* Aq = g_q  + (size_t)n * CH  * Ss + (size_t)h * Cc * Ss;
    const float* Ak = g_kv + (size_t)n * KV2 * Ss + (size_t)h * Cc * Ss;
    int m0 = blockIdx.y * 64;      // qs
    int j0 = blockIdx.x * 64;      // ks

    __shared__ float As[16][68], Bs[16][68];
    float acc[4][4] = {};
    int tid = threadIdx.x;
    int tx = tid & 15, ty = tid >> 4;
    int bj = (tid & 15) * 4, bk = tid >> 4;

    for (int k0 = 0; k0 < Cc; k0 += 16) {
        float4 a4 = *(const float4*)&Aq[(size_t)(k0 + bk) * Ss + m0 + bj];
        *(float4*)&As[bk][bj] = a4;
        float4 b4 = *(const float4*)&Ak[(size_t)(k0 + bk) * Ss + j0 + bj];
        *(float4*)&Bs[bk][bj] = b4;
        __syncthreads();
        mm_tile(As, Bs, acc, tx, ty);
        __syncthreads();
    }
    float* Cp = g_att + (size_t)z * Ss * Ss;
#pragma unroll
    for (int i = 0; i < 4; i++) {
        int m = m0 + ty * 4 + i;
        float4 o = {acc[i][0] * SCALE2, acc[i][1] * SCALE2,
                    acc[i][2] * SCALE2, acc[i][3] * SCALE2};
        *(float4*)&Cp[(size_t)m * Ss + j0 + tx * 4] = o;
    }
}

// ---------------------------------------------------------------------------
// Softmax over last dim of g_att (one block per row of 2048)
// ---------------------------------------------------------------------------
__global__ __launch_bounds__(256) void softmax_kernel() {
    float* p = g_att + (size_t)blockIdx.x * Ss;
    int t = threadIdx.x;
    float v[8];
    float mx = -1e30f;
#pragma unroll
    for (int i = 0; i < 8; i++) { v[i] = p[t + i * 256]; mx = fmaxf(mx, v[i]); }
    __shared__ float sh[256];
    sh[t] = mx; __syncthreads();
    for (int o = 128; o > 0; o >>= 1) {
        if (t < o) sh[t] = fmaxf(sh[t], sh[t + o]);
        __syncthreads();
    }
    mx = sh[0];
    __syncthreads();
    float s = 0.f;
#pragma unroll
    for (int i = 0; i < 8; i++) { v[i] = __expf(v[i] - mx); s += v[i]; }
    sh[t] = s; __syncthreads();
    for (int o = 128; o > 0; o >>= 1) {
        if (t < o) sh[t] += sh[t + o];
        __syncthreads();
    }
    float inv = 1.0f / sh[0];
#pragma unroll
    for (int i = 0; i < 8; i++) p[t + i * 256] = v[i] * inv;
}

// ---------------------------------------------------------------------------
// GEMM 4: y[c,qs] = sum_ks v[c,ks] * att[qs,ks]    (A @ B^T via transposed B load)
// ---------------------------------------------------------------------------
__global__ __launch_bounds__(256) void gemm_y_kernel() {
    int z = blockIdx.z;            // n*8 + h
    int n = z >> 3, h = z & 7;
    const float* A   = g_kv + (size_t)n * KV2 * Ss + (size_t)(Hh + h) * Cc * Ss; // v[c][ks]
    const float* att = g_att + (size_t)z * Ss * Ss;                               // att[qs][ks]
    int m0 = blockIdx.y * 64;      // c   (512 -> 8 tiles)
    int j0 = blockIdx.x * 64;      // qs

    __shared__ float As[16][68], Bs[16][68];
    float acc[4][4] = {};
    int tid = threadIdx.x;
    int tx = tid & 15, ty = tid >> 4;
    int ac = (tid & 3) * 4, ar = tid >> 2;

    for (int k0 = 0; k0 < Ss; k0 += 16) {
        float4 a4 = *(const float4*)&A[(size_t)(m0 + ar) * Ss + k0 + ac];
        As[ac + 0][ar] = a4.x; As[ac + 1][ar] = a4.y;
        As[ac + 2][ar] = a4.z; As[ac + 3][ar] = a4.w;
        float4 b4 = *(const float4*)&att[(size_t)(j0 + ar) * Ss + k0 + ac];
        Bs[ac + 0][ar] = b4.x; Bs[ac + 1][ar] = b4.y;
        Bs[ac + 2][ar] = b4.z; Bs[ac + 3][ar] = b4.w;
        __syncthreads();
        mm_tile(As, Bs, acc, tx, ty);
        __syncthreads();
    }
    float* Cp = g_y + (size_t)n * CH * Ss + (size_t)h * Cc * Ss;
#pragma unroll
    for (int i = 0; i < 4; i++) {
        int m = m0 + ty * 4 + i;
        float4 o = {acc[i][0], acc[i][1], acc[i][2], acc[i][3]};
        *(float4*)&Cp[(size_t)m * Ss + j0 + tx * 4] = o;
    }
}

// ---------------------------------------------------------------------------
// GEMM 5: out = Wo @ y + bo + input (residual)   (per n: [512x4096] @ [4096x2048])
// ---------------------------------------------------------------------------
__global__ __launch_bounds__(256) void gemm_out_kernel(
    const float* __restrict__ Wo, const float* __restrict__ bo,
    const float* __restrict__ input, float* __restrict__ out)
{
    int n  = blockIdx.z;
    int m0 = blockIdx.y * 64;
    int j0 = blockIdx.x * 64;
    const float* B = g_y + (size_t)n * CH * Ss;

    __shared__ float As[16][68], Bs[16][68];
    float acc[4][4] = {};
    int tid = threadIdx.x;
    int tx = tid & 15, ty = tid >> 4;
    int ac = (tid & 3) * 4, ar = tid >> 2;
    int bj = (tid & 15) * 4, bk = tid >> 4;

    for (int k0 = 0; k0 < CH; k0 += 16) {
        float4 a4 = *(const float4*)&Wo[(size_t)(m0 + ar) * CH + k0 + ac];
        As[ac + 0][ar] = a4.x; As[ac + 1][ar] = a4.y;
        As[ac + 2][ar] = a4.z; As[ac + 3][ar] = a4.w;
        float4 b4 = *(const float4*)&B[(size_t)(k0 + bk) * Ss + j0 + bj];
        *(float4*)&Bs[bk][bj] = b4;
        __syncthreads();
        mm_tile(As, Bs, acc, tx, ty);
        __syncthreads();
    }
#pragma unroll
    for (int i = 0; i < 4; i++) {
        int m = m0 + ty * 4 + i;
        float bi = bo[m];
        size_t idx = (size_t)n * Cc * Ss + (size_t)m * Ss + j0 + tx * 4;
        float4 r = *(const float4*)&input[idx];
        float4 o = {acc[i][0] + bi + r.x, acc[i][1] + bi + r.y,
                    acc[i][2] + bi + r.z, acc[i][3] + bi + r.w};
        *(float4*)&out[idx] = o;
    }
}

// ---------------------------------------------------------------------------
extern "C" void kernel_launch(void* const* d_in, const int* in_sizes, int n_in,
                              void* d_out, int out_size) {
    const float* input   = (const float*)d_in[0];
    const float* context = (const float*)d_in[1];
    const float* gamma   = (const float*)d_in[2];
    const float* beta    = (const float*)d_in[3];
    const float* Wq      = (const float*)d_in[4];
    const float* bq      = (const float*)d_in[5];
    const float* Wkv     = (const float*)d_in[6];
    const float* bkv     = (const float*)d_in[7];
    const float* Wo      = (const float*)d_in[8];
    const float* bo      = (const float*)d_in[9];
    float* out = (float*)d_out;

    // LayerNorm stats
    ln_part_kernel<<<dim3(128, Nn), 256>>>(input);
    ln_fin_kernel<<<Nn, 128>>>();

    // Projections
    gemm_q_kernel <<<dim3(Ss / 64, CH  / 64, Nn), 256>>>(Wq, bq, input, gamma, beta);
    gemm_kv_kernel<<<dim3(Ss / 64, KV2 / 64, Nn), 256>>>(Wkv, bkv, context);

    // Attention
    gemm_scores_kernel<<<dim3(Ss / 64, Ss / 64, Nn * Hh), 256>>>();
    softmax_kernel<<<Nn * Hh * Ss, 256>>>();
    gemm_y_kernel<<<dim3(Ss / 64, Cc / 64, Nn * Hh), 256>>>();

    // Output projection + residual
    gemm_out_kernel<<<dim3(Ss / 64, Cc / 64, Nn), 256>>>(Wo, bo, input, out);
}

// round 2
// speedup vs baseline: 1.0088x; 1.0088x over previous
#include <cuda_runtime.h>
#include <mma.h>
#include <type_traits>

using namespace nvcuda;

// Problem constants
#define Nn   4
#define Cc   512
#define Ss   2048
#define Hh   8
#define CH   4096    // C*H
#define CTXD 512

#define SCALE2 0.044194173824159216f   // 512^-0.5

// Scratch (device globals — allocation-free rule)
__device__ float g_q  [(size_t)Nn * CH * Ss];     // 128 MB
__device__ float g_k  [(size_t)Nn * CH * Ss];     // 128 MB
__device__ float g_v  [(size_t)Nn * CH * Ss];     // 128 MB
__device__ float g_att[(size_t)Nn * Hh * Ss * Ss];// 512 MB
__device__ float g_y  [(size_t)Nn * CH * Ss];     // 128 MB
__device__ float g_part[Nn * 128 * 2];
__device__ float g_stats[Nn * 2];                 // mu, rsigma per sample

// ---------------------------------------------------------------------------
// LayerNorm statistics
// ---------------------------------------------------------------------------
__global__ void ln_part_kernel(const float* __restrict__ x) {
    int n = blockIdx.y;
    int b = blockIdx.x;                       // 0..127
    const int chunk = (Cc * Ss) / 128;        // 8192 floats
    const float4* p4 = (const float4*)(x + (size_t)n * Cc * Ss + (size_t)b * chunk);
    float s = 0.f, s2 = 0.f;
    for (int i = threadIdx.x; i < chunk / 4; i += 256) {
        float4 v = p4[i];
        s  += v.x + v.y + v.z + v.w;
        s2 += v.x * v.x + v.y * v.y + v.z * v.z + v.w * v.w;
    }
    __shared__ float sh0[256], sh1[256];
    sh0[threadIdx.x] = s; sh1[threadIdx.x] = s2;
    __syncthreads();
    for (int o = 128; o > 0; o >>= 1) {
        if (threadIdx.x < o) {
            sh0[threadIdx.x] += sh0[threadIdx.x + o];
            sh1[threadIdx.x] += sh1[threadIdx.x + o];
        }
        __syncthreads();
    }
    if (threadIdx.x == 0) {
        g_part[(n * 128 + b) * 2 + 0] = sh0[0];
        g_part[(n * 128 + b) * 2 + 1] = sh1[0];
    }
}

__global__ void ln_fin_kernel() {
    int n = blockIdx.x;
    int t = threadIdx.x;  // 128 threads
    float s  = g_part[(n * 128 + t) * 2 + 0];
    float s2 = g_part[(n * 128 + t) * 2 + 1];
    __shared__ float sh0[128], sh1[128];
    sh0[t] = s; sh1[t] = s2;
    __syncthreads();
    for (int o = 64; o > 0; o >>= 1) {
        if (t < o) { sh0[t] += sh0[t + o]; sh1[t] += sh1[t + o]; }
        __syncthreads();
    }
    if (t == 0) {
        const float inv = 1.0f / (float)(Cc * Ss);
        float mu  = sh0[0] * inv;
        float var = sh1[0] * inv - mu * mu;
        g_stats[n * 2 + 0] = mu;
        g_stats[n * 2 + 1] = rsqrtf(var + 1e-5f);
    }
}

// ---------------------------------------------------------------------------
// TF32 tensor-core GEMM, 128x128x16 tiles, double-buffered, 8 warps.
//  AMK:  true  -> A is [M][K] row-major   (matrix_a row_major)
//        false -> A is [K][M]             (matrix_a col_major)
//  BKN:  true  -> B is [K][N]             (matrix_b row_major)
//        false -> B is [N][K]             (matrix_b col_major)
//  EPI:  0 = direct store, 1 = +bias[m], 2 = *SCALE2, 3 = +bias[m] + residual
//  LN:   apply (x*g + b) transform to B rows (per-k gamma/beta with batch stats)
// ---------------------------------------------------------------------------
__device__ __forceinline__ float t32(float x) { return wmma::__float_to_tf32(x); }

template<bool AMK, bool BKN, int EPI, bool LN>
__global__ __launch_bounds__(256) void tc_gemm(
    const float* __restrict__ A, size_t lda, size_t aStride,
    const float* __restrict__ B, size_t ldb, size_t bStride,
    float* __restrict__ C, size_t ldc, size_t cStride,
    const float* __restrict__ bias,
    const float* __restrict__ resid, size_t rStride,
    const float* __restrict__ gamma, const float* __restrict__ beta,
    int kTotal)
{
    constexpr int BM = 128, BN = 128, BK = 16;
    using ALayout = typename std::conditional<AMK, wmma::row_major, wmma::col_major>::type;
    using BLayout = typename std::conditional<BKN, wmma::row_major, wmma::col_major>::type;

    const int batch = blockIdx.z;
    const int m0 = blockIdx.y * BM;
    const int j0 = blockIdx.x * BN;
    const float* Ab = A + (size_t)batch * aStride;
    const float* Bb = B + (size_t)batch * bStride;
    float*       Cb = C + (size_t)batch * cStride;

    // smem: two buffers of (A tile 3072 floats, B tile 3072 floats) = 48 KB
    __shared__ float smem[12288];

    const int tid  = threadIdx.x;
    const int warp = tid >> 5;
    const int lane = tid & 31;
    const int wm = warp >> 2;      // 0..1
    const int wn = warp & 3;       // 0..3

    float mu = 0.f, rs = 0.f;
    if (LN) { mu = g_stats[batch * 2 + 0]; rs = g_stats[batch * 2 + 1]; }

    wmma::fragment<wmma::accumulator, 16, 16, 8, float> acc[4][2];
#pragma unroll
    for (int i = 0; i < 4; i++)
#pragma unroll
        for (int j = 0; j < 2; j++)
            wmma::fill_fragment(acc[i][j], 0.0f);

    float4 ra[2], rb[2];
    // per-thread k-row index for LN coefficients (B KN loader)
    float lnG[2], lnB[2];

    auto loadA = [&](int k0) {
#pragma unroll
        for (int i = 0; i < 2; i++) {
            int idx = i * 256 + tid;
            if (AMK) {
                int row = idx >> 2, kq = (idx & 3) << 2;
                ra[i] = *(const float4*)&Ab[(size_t)(m0 + row) * lda + k0 + kq];
            } else {
                int krow = idx >> 5, mq = (idx & 31) << 2;
                ra[i] = *(const float4*)&Ab[(size_t)(k0 + krow) * lda + m0 + mq];
            }
        }
    };
    auto loadB = [&](int k0) {
#pragma unroll
        for (int i = 0; i < 2; i++) {
            int idx = i * 256 + tid;
            if (BKN) {
                int krow = idx >> 5, nq = (idx & 31) << 2;
                rb[i] = *(const float4*)&Bb[(size_t)(k0 + krow) * ldb + j0 + nq];
                if (LN) {
                    int c = k0 + krow;
                    float g = gamma[c] * rs;
                    lnG[i] = g;
                    lnB[i] = beta[c] - mu * g;
                }
            } else {
                int row = idx >> 2, kq = (idx & 3) << 2;
                rb[i] = *(const float4*)&Bb[(size_t)(j0 + row) * ldb + k0 + kq];
            }
        }
    };
    auto storeA = [&](float* dst) {
#pragma unroll
        for (int i = 0; i < 2; i++) {
            int idx = i * 256 + tid;
            float4 v = ra[i];
            if (AMK) {
                int row = idx >> 2, kq = (idx & 3) << 2;
                float* p = &dst[row * 24 + kq];
                p[0] = t32(v.x); p[1] = t32(v.y); p[2] = t32(v.z); p[3] = t32(v.w);
            } else {
                int krow = idx >> 5, mq = (idx & 31) << 2;
                float* p = &dst[krow * 136 + mq];
                p[0] = t32(v.x); p[1] = t32(v.y); p[2] = t32(v.z); p[3] = t32(v.w);
            }
        }
    };
    auto storeB = [&](float* dst) {
#pragma unroll
        for (int i = 0; i < 2; i++) {
            int idx = i * 256 + tid;
            float4 v = rb[i];
            if (BKN) {
                int krow = idx >> 5, nq = (idx & 31) << 2;
                if (LN) {
                    v.x = v.x * lnG[i] + lnB[i]; v.y = v.y * lnG[i] + lnB[i];
                    v.z = v.z * lnG[i] + lnB[i]; v.w = v.w * lnG[i] + lnB[i];
                }
                float* p = &dst[krow * 136 + nq];
                p[0] = t32(v.x); p[1] = t32(v.y); p[2] = t32(v.z); p[3] = t32(v.w);
            } else {
                int row = idx >> 2, kq = (idx & 3) << 2;
                float* p = &dst[row * 24 + kq];
                p[0] = t32(v.x); p[1] = t32(v.y); p[2] = t32(v.z); p[3] = t32(v.w);
            }
        }
    };

    const int nt = kTotal / BK;
    loadA(0); loadB(0);
    storeA(smem); storeB(smem + 3072);
    __syncthreads();

    for (int t = 0; t < nt; t++) {
        float* curA = smem + (t & 1) * 6144;
        float* curB = curA + 3072;
        if (t + 1 < nt) { loadA((t + 1) * BK); loadB((t + 1) * BK); }

#pragma unroll
        for (int ks = 0; ks < BK; ks += 8) {
            wmma::fragment<wmma::matrix_a, 16, 16, 8, wmma::precision::tf32, ALayout> af[4];
            wmma::fragment<wmma::matrix_b, 16, 16, 8, wmma::precision::tf32, BLayout> bf[2];
#pragma unroll
            for (int i = 0; i < 4; i++) {
                if (AMK)
                    wmma::load_matrix_sync(af[i], curA + (wm * 64 + i * 16) * 24 + ks, 24);
                else
                    wmma::load_matrix_sync(af[i], curA + ks * 136 + wm * 64 + i * 16, 136);
            }
#pragma unroll
            for (int j = 0; j < 2; j++) {
                if (BKN)
                    wmma::load_matrix_sync(bf[j], curB + ks * 136 + wn * 32 + j * 16, 136);
                else
                    wmma::load_matrix_sync(bf[j], curB + (wn * 32 + j * 16) * 24 + ks, 24);
            }
#pragma unroll
            for (int i = 0; i < 4; i++)
#pragma unroll
                for (int j = 0; j < 2; j++)
                    wmma::mma_sync(acc[i][j], af[i], bf[j], acc[i][j]);
        }

        if (t + 1 < nt) {
            float* nA = smem + ((t + 1) & 1) * 6144;
            storeA(nA); storeB(nA + 3072);
        }
        __syncthreads();
    }

    // Epilogue
    if (EPI == 0) {
#pragma unroll
        for (int i = 0; i < 4; i++)
#pragma unroll
            for (int j = 0; j < 2; j++)
                wmma::store_matrix_sync(
                    Cb + (size_t)(m0 + wm * 64 + i * 16) * ldc + j0 + wn * 32 + j * 16,
                    acc[i][j], ldc, wmma::mem_row_major);
    } else {
        float* stg = smem + warp * 256;
        const float* Rb = (EPI == 3) ? (resid + (size_t)batch * rStride) : nullptr;
#pragma unroll
        for (int i = 0; i < 4; i++) {
#pragma unroll
            for (int j = 0; j < 2; j++) {
                wmma::store_matrix_sync(stg, acc[i][j], 16, wmma::mem_row_major);
                __syncwarp();
                int r  = lane >> 1;
                int c0 = (lane & 1) * 8;
                int m  = m0 + wm * 64 + i * 16 + r;
                size_t off = (size_t)m * ldc + j0 + wn * 32 + j * 16 + c0;
                float v[8];
#pragma unroll
                for (int e = 0; e < 8; e++) v[e] = stg[r * 16 + c0 + e];
                if (EPI == 1 || EPI == 3) {
                    float bi = bias[m];
#pragma unroll
                    for (int e = 0; e < 8; e++) v[e] += bi;
                }
                if (EPI == 2) {
#pragma unroll
                    for (int e = 0; e < 8; e++) v[e] *= SCALE2;
                }
                if (EPI == 3) {
                    float4 r0 = *(const float4*)&Rb[off];
                    float4 r1 = *(const float4*)&Rb[off + 4];
                    v[0] += r0.x; v[1] += r0.y; v[2] += r0.z; v[3] += r0.w;
                    v[4] += r1.x; v[5] += r1.y; v[6] += r1.z; v[7] += r1.w;
                }
                float4 o0 = {v[0], v[1], v[2], v[3]};
                float4 o1 = {v[4], v[5], v[6], v[7]};
                *(float4*)&Cb[off]     = o0;
                *(float4*)&Cb[off + 4] = o1;
                __syncwarp();
            }
        }
    }
}

// ---------------------------------------------------------------------------
// Softmax over last dim of g_att (one block per row of 2048)
// ---------------------------------------------------------------------------
__global__ __launch_bounds__(256) void softmax_kernel() {
    float* p = g_att + (size_t)blockIdx.x * Ss;
    int t = threadIdx.x;
    float v[8];
    float mx = -1e30f;
#pragma unroll
    for (int i = 0; i < 8; i++) { v[i] = p[t + i * 256]; mx = fmaxf(mx, v[i]); }
    __shared__ float sh[256];
    sh[t] = mx; __syncthreads();
    for (int o = 128; o > 0; o >>= 1) {
        if (t < o) sh[t] = fmaxf(sh[t], sh[t + o]);
        __syncthreads();
    }
    mx = sh[0];
    __syncthreads();
    float s = 0.f;
#pragma unroll
    for (int i = 0; i < 8; i++) { v[i] = __expf(v[i] - mx); s += v[i]; }
    sh[t] = s; __syncthreads();
    for (int o = 128; o > 0; o >>= 1) {
        if (t < o) sh[t] += sh[t + o];
        __syncthreads();
    }
    float inv = 1.0f / sh[0];
#pragma unroll
    for (int i = 0; i < 8; i++) p[t + i * 256] = v[i] * inv;
}

// ---------------------------------------------------------------------------
extern "C" void kernel_launch(void* const* d_in, const int* in_sizes, int n_in,
                              void* d_out, int out_size) {
    const float* input   = (const float*)d_in[0];
    const float* context = (const float*)d_in[1];
    const float* gamma   = (const float*)d_in[2];
    const float* beta    = (const float*)d_in[3];
    const float* Wq      = (const float*)d_in[4];
    const float* bq      = (const float*)d_in[5];
    const float* Wkv     = (const float*)d_in[6];
    const float* bkv     = (const float*)d_in[7];
    const float* Wo      = (const float*)d_in[8];
    const float* bo      = (const float*)d_in[9];
    float* out = (float*)d_out;

    const size_t CS  = (size_t)Cc * Ss;     // 1M
    const size_t CHS = (size_t)CH * Ss;     // 8M
    const size_t SSq = (size_t)Ss * Ss;     // 4M

    // LayerNorm stats
    ln_part_kernel<<<dim3(128, Nn), 256>>>(input);
    ln_fin_kernel<<<Nn, 128>>>();

    float* g_q_p   = nullptr; cudaGetSymbolAddress((void**)&g_q_p,   g_q);
    float* g_k_p   = nullptr; cudaGetSymbolAddress((void**)&g_k_p,   g_k);
    float* g_v_p   = nullptr; cudaGetSymbolAddress((void**)&g_v_p,   g_v);
    float* g_att_p = nullptr; cudaGetSymbolAddress((void**)&g_att_p, g_att);
    float* g_y_p   = nullptr; cudaGetSymbolAddress((void**)&g_y_p,   g_y);

    // Q = Wq @ LN(input) + bq       [4096x512]@[512x2048] per n
    tc_gemm<true, true, 1, true><<<dim3(Ss / 128, CH / 128, Nn), 256>>>(
        Wq, Cc, 0, input, Ss, CS, g_q_p, Ss, CHS,
        bq, nullptr, 0, gamma, beta, Cc);

    // K = Wkv[0:4096] @ context + bkv[0:4096]
    tc_gemm<true, true, 1, false><<<dim3(Ss / 128, CH / 128, Nn), 256>>>(
        Wkv, CTXD, 0, context, Ss, (size_t)CTXD * Ss, g_k_p, Ss, CHS,
        bkv, nullptr, 0, nullptr, nullptr, CTXD);

    // V = Wkv[4096:8192] @ context + bkv[4096:8192]
    tc_gemm<true, true, 1, false><<<dim3(Ss / 128, CH / 128, Nn), 256>>>(
        Wkv + (size_t)CH * CTXD, CTXD, 0, context, Ss, (size_t)CTXD * Ss, g_v_p, Ss, CHS,
        bkv + CH, nullptr, 0, nullptr, nullptr, CTXD);

    // scores[q,ks] = SCALE2 * q^T k    (A [c][q] col-mode, B [c][ks])
    tc_gemm<false, true, 2, false><<<dim3(Ss / 128, Ss / 128, Nn * Hh), 256>>>(
        g_q_p, Ss, CS, g_k_p, Ss, CS, g_att_p, Ss, SSq,
        nullptr, nullptr, 0, nullptr, nullptr, Cc);

    softmax_kernel<<<Nn * Hh * Ss, 256>>>();

    // y[c,q] = v @ att^T    (A [c][ks], B att [q][ks] col-mode)
    tc_gemm<true, false, 0, false><<<dim3(Ss / 128, Cc / 128, Nn * Hh), 256>>>(
        g_v_p, Ss, CS, g_att_p, Ss, SSq, g_y_p, Ss, CS,
        nullptr, nullptr, 0, nullptr, nullptr, Ss);

    // out = Wo @ y + bo + input     [512x4096]@[4096x2048] per n
    tc_gemm<true, true, 3, false><<<dim3(Ss / 128, Cc / 128, Nn), 256>>>(
        Wo, CH, 0, g_y_p, Ss, CHS, out, Ss, CS,
        bo, input, CS, nullptr, nullptr, CH);
}

// round 4
// speedup vs baseline: 4.7725x; 4.7308x over previous
#include <cuda_runtime.h>
#include <cuda_fp16.h>
#include <cstdint>

// ===========================================================================
// Problem constants
// ===========================================================================
#define Nn   4
#define Cc   512
#define Ss   2048
#define Hh   8
#define CH   4096    // C*H
#define CTXD 512

#define SCALE2 0.044194173824159216f   // 512^-0.5
#define LNEPS  1e-5f

// ===========================================================================
// PTX helpers (plain sm_103-compatible: mma.sync / ldmatrix / cp.async)
// ===========================================================================
__device__ __forceinline__ uint32_t smem_to_u32(const void* smem_ptr) {
    uint32_t addr;
    asm("{ .reg .u64 tmp; cvta.to.shared.u64 tmp, %1; cvt.u32.u64 %0, tmp; }"
        : "=r"(addr) : "l"(smem_ptr));
    return addr;
}

__device__ __forceinline__ void cpa16(uint32_t s, const void* g) {
    asm volatile("cp.async.cg.shared.global [%0], [%1], 16;" :: "r"(s), "l"(g));
}
#define CP_COMMIT() asm volatile("cp.async.commit_group;" ::: "memory")
#define CP_WAIT(n)  asm volatile("cp.async.wait_group %0;" :: "n"(n) : "memory")

__device__ __forceinline__ void ldm_x4(uint32_t* r, uint32_t saddr) {
    asm volatile("ldmatrix.sync.aligned.m8n8.x4.shared.b16 {%0,%1,%2,%3}, [%4];"
        : "=r"(r[0]), "=r"(r[1]), "=r"(r[2]), "=r"(r[3]) : "r"(saddr));
}

__device__ __forceinline__ void mma16816(float* c, const uint32_t* a,
                                         uint32_t b0, uint32_t b1) {
    asm volatile(
        "mma.sync.aligned.m16n8k16.row.col.f32.f16.f16.f32 "
        "{%0,%1,%2,%3},{%4,%5,%6,%7},{%8,%9},{%0,%1,%2,%3};"
        : "+f"(c[0]), "+f"(c[1]), "+f"(c[2]), "+f"(c[3])
        : "r"(a[0]), "r"(a[1]), "r"(a[2]), "r"(a[3]), "r"(b0), "r"(b1));
}

__device__ __forceinline__ uint32_t packh2(float a, float b) {
    __half2 h = __floats2half2_rn(a, b);
    return *(uint32_t*)&h;
}

// ===========================================================================
// Scratch (device globals — allocation-free rule)
// ===========================================================================
__device__ __half g_wq [(size_t)CH * Cc];
__device__ __half g_wkv[(size_t)2 * CH * CTXD];
__device__ __half g_wo [(size_t)Cc * CH];
__device__ __half g_xnT [(size_t)Nn * Ss * Cc];      // [n][s][c]
__device__ __half g_ctxT[(size_t)Nn * Ss * CTXD];    // [n][s][d]
__device__ __half g_qT [(size_t)Nn * Hh * Ss * Cc];  // [n][h][s][c]
__device__ __half g_kT [(size_t)Nn * Hh * Ss * Cc];
__device__ __half g_vb [(size_t)Nn * CH * Ss];       // [n][o][s]
__device__ float  g_att [(size_t)Nn * Hh * Ss * Ss]; // fp32 scores
__device__ __half g_attp[(size_t)Nn * Hh * Ss * Ss]; // softmax probs
__device__ __half g_yT [(size_t)Nn * Ss * CH];       // [n][s][o]
__device__ float g_part[Nn * 128 * 2];
__device__ float g_stats[Nn * 2];

// ===========================================================================
// LayerNorm statistics
// ===========================================================================
__global__ void ln_part_kernel(const float* __restrict__ x) {
    int n = blockIdx.y, b = blockIdx.x;
    const int chunk = (Cc * Ss) / 128;
    const float4* p4 = (const float4*)(x + (size_t)n * Cc * Ss + (size_t)b * chunk);
    float s = 0.f, s2 = 0.f;
    for (int i = threadIdx.x; i < chunk / 4; i += 256) {
        float4 v = p4[i];
        s  += v.x + v.y + v.z + v.w;
        s2 += v.x * v.x + v.y * v.y + v.z * v.z + v.w * v.w;
    }
    __shared__ float sh0[256], sh1[256];
    sh0[threadIdx.x] = s; sh1[threadIdx.x] = s2;
    __syncthreads();
    for (int o = 128; o > 0; o >>= 1) {
        if (threadIdx.x < o) {
            sh0[threadIdx.x] += sh0[threadIdx.x + o];
            sh1[threadIdx.x] += sh1[threadIdx.x + o];
        }
        __syncthreads();
    }
    if (threadIdx.x == 0) {
        g_part[(n * 128 + b) * 2 + 0] = sh0[0];
        g_part[(n * 128 + b) * 2 + 1] = sh1[0];
    }
}

__global__ void ln_fin_kernel() {
    int n = blockIdx.x, t = threadIdx.x;
    float s  = g_part[(n * 128 + t) * 2 + 0];
    float s2 = g_part[(n * 128 + t) * 2 + 1];
    __shared__ float sh0[128], sh1[128];
    sh0[t] = s; sh1[t] = s2;
    __syncthreads();
    for (int o = 64; o > 0; o >>= 1) {
        if (t < o) { sh0[t] += sh0[t + o]; sh1[t] += sh1[t + o]; }
        __syncthreads();
    }
    if (t == 0) {
        const float inv = 1.0f / (float)(Cc * Ss);
        float mu  = sh0[0] * inv;
        float var = sh1[0] * inv - mu * mu;
        g_stats[n * 2 + 0] = mu;
        g_stats[n * 2 + 1] = rsqrtf(var + LNEPS);
    }
}

// ===========================================================================
// Prep: transpose fp32 [z][R][S] -> fp16 [z][S][R], optional LN affine by row
// ===========================================================================
template<bool LN>
__global__ void prepT_kernel(const float* __restrict__ X, __half* __restrict__ O,
                             const float* __restrict__ gamma, const float* __restrict__ beta,
                             int R, int S)
{
    __shared__ float tile[32][33];
    int z = blockIdx.z;
    int s0 = blockIdx.x * 32, r0 = blockIdx.y * 32;
    const float* Xb = X + (size_t)z * R * S;
    __half* Ob = O + (size_t)z * R * S;
    float mu = 0.f, rs = 0.f;
    if (LN) { mu = g_stats[z * 2 + 0]; rs = g_stats[z * 2 + 1]; }
    int tx = threadIdx.x, ty = threadIdx.y;
#pragma unroll
    for (int i = 0; i < 32; i += 8) {
        int r = r0 + ty + i;
        float val = Xb[(size_t)r * S + s0 + tx];
        if (LN) {
            float g = gamma[r] * rs;
            val = val * g + (beta[r] - mu * g);
        }
        tile[ty + i][tx] = val;
    }
    __syncthreads();
#pragma unroll
    for (int i = 0; i < 32; i += 8) {
        int s = s0 + ty + i;
        Ob[(size_t)s * R + r0 + tx] = __float2half_rn(tile[tx][ty + i]);
    }
}

// fp32 -> fp16 elementwise (n4 = elements/4)
__global__ void f2h_kernel(const float* __restrict__ X, __half* __restrict__ O, int n4) {
    int i = blockIdx.x * 256 + threadIdx.x;
    if (i < n4) {
        float4 v = ((const float4*)X)[i];
        __half2* o = (__half2*)O + (size_t)i * 2;
        o[0] = __floats2half2_rn(v.x, v.y);
        o[1] = __floats2half2_rn(v.z, v.w);
    }
}

// ===========================================================================
// fp16 mma.sync GEMM: 128x128 tiles, BK=32, 3-stage cp.async pipeline.
// A: [Mrows][K] K-major fp16.  B: [Nrows][K] K-major fp16.  D = A · B^T (fp32).
// EPI: 0 = scores fp32 *SCALE2
//      1 = V fp16 +bias            (C: [z][m][j])
//      2 = Q/K fp16 transposed+bias(C: [(z*8+h)][s][c])
//      3 = y fp16 transposed       (C: [n][s][h*512+m])
//      4 = out fp32 +bias +residual
// SMEM per stage: A 128x40 halfs (80B rows) + B same = 20480 B; 3 stages.
// Epilogue staging reuses smem as fp32 [128][130].
// ===========================================================================
#define ROWB   80          // bytes per smem row (32 halfs data + 8 pad)
#define STAGEB 20480       // bytes per pipeline stage
#define GEMM_SMEM 66560    // max(3*20480, 128*130*4) = 66560

template<int EPI>
__global__ __launch_bounds__(256, 2) void hgemm(
    const __half* __restrict__ A, size_t lda, size_t aStr,
    const __half* __restrict__ B, size_t ldb, size_t bStr,
    void* __restrict__ Cv,
    const float* __restrict__ bias,
    const float* __restrict__ resid,
    int nt)
{
    extern __shared__ __align__(1024) char smem[];
    const uint32_t sb = smem_to_u32(smem);

    const int tid  = threadIdx.x;
    const int warp = tid >> 5;
    const int lane = tid & 31;
    const int wm = warp >> 2;        // 0..1
    const int wn = warp & 3;         // 0..3
    const int z  = blockIdx.z;
    const int m0 = blockIdx.y * 128;
    const int j0 = blockIdx.x * 128;

    const __half* Ab = A + (size_t)z * aStr + (size_t)(m0 + (tid >> 1)) * lda;
    const __half* Bb = B + (size_t)z * bStr + (size_t)(j0 + (tid >> 1)) * ldb;

    // loader coords: row = tid>>1 (0..127), two 16B segs at (tid&1)*32B
    const uint32_t srowA = sb + (uint32_t)(tid >> 1) * ROWB + (uint32_t)(tid & 1) * 32;
    const uint32_t srowB = srowA + 10240;
    const int gseg = (tid & 1) * 16;   // halfs offset

    auto prefetch = [&](int kt, int buf) {
        uint32_t so = (uint32_t)buf * STAGEB;
        const __half* ga = Ab + (size_t)kt * 32 + gseg;
        const __half* gb = Bb + (size_t)kt * 32 + gseg;
        cpa16(srowA + so,      ga);
        cpa16(srowA + so + 16, ga + 8);
        cpa16(srowB + so,      gb);
        cpa16(srowB + so + 16, gb + 8);
    };

    float acc[4][4][4];
#pragma unroll
    for (int i = 0; i < 4; i++)
#pragma unroll
        for (int j = 0; j < 4; j++)
#pragma unroll
            for (int e = 0; e < 4; e++) acc[i][j][e] = 0.f;

    // ldmatrix lane coords (same pattern for A and B: x4 over 16 rows x 16 halfs)
    const int lrow = lane & 15;                 // row within 16-row tile
    const int lcolb = (lane >> 4) * 16;         // byte offset of 8-half col seg

    prefetch(0, 0); CP_COMMIT();
    if (nt > 1) prefetch(1, 1);
    CP_COMMIT();

    for (int t = 0; t < nt; t++) {
        if (t + 2 < nt) prefetch(t + 2, (t + 2) % 3);
        CP_COMMIT();
        CP_WAIT(2);
        __syncthreads();

        uint32_t aB = sb + (uint32_t)((t % 3) * STAGEB);
        uint32_t bB = aB + 10240;
#pragma unroll
        for (int ks = 0; ks < 2; ks++) {
            uint32_t colb = (uint32_t)(ks * 32 + lcolb);
            uint32_t a[4][4], bf[2][4];
#pragma unroll
            for (int i = 0; i < 4; i++)
                ldm_x4(a[i], aB + (uint32_t)(wm * 64 + i * 16 + lrow) * ROWB + colb);
#pragma unroll
            for (int p = 0; p < 2; p++)
                ldm_x4(bf[p], bB + (uint32_t)(wn * 32 + p * 16 + lrow) * ROWB + colb);
#pragma unroll
            for (int i = 0; i < 4; i++) {
#pragma unroll
                for (int p = 0; p < 2; p++) {
                    mma16816(acc[i][p * 2 + 0], a[i], bf[p][0], bf[p][2]);
                    mma16816(acc[i][p * 2 + 1], a[i], bf[p][1], bf[p][3]);
                }
            }
        }
        __syncthreads();
    }

    // ---- stage D (fp32) into smem [128][130] ----
    float* stg = (float*)smem;
    {
        int r = lane >> 2, cq = (lane & 3) * 2;
#pragma unroll
        for (int i = 0; i < 4; i++) {
            int row = wm * 64 + i * 16 + r;
#pragma unroll
            for (int j = 0; j < 4; j++) {
                int col = wn * 32 + j * 8 + cq;
                float2 lo = {acc[i][j][0], acc[i][j][1]};
                float2 hi = {acc[i][j][2], acc[i][j][3]};
                *(float2*)&stg[(size_t)row * 130 + col]       = lo;
                *(float2*)&stg[(size_t)(row + 8) * 130 + col] = hi;
            }
        }
    }
    __syncthreads();

    // ---- output phase ----
    if (EPI == 0) {              // scores fp32 * SCALE2
        int r = tid >> 1, ch = tid & 1;
        const float* sp = stg + (size_t)r * 130 + ch * 64;
        float* dst = (float*)Cv + (size_t)z * Ss * Ss + (size_t)(m0 + r) * Ss + j0 + ch * 64;
#pragma unroll
        for (int i = 0; i < 64; i += 4) {
            float4 v = {sp[i] * SCALE2, sp[i + 1] * SCALE2,
                        sp[i + 2] * SCALE2, sp[i + 3] * SCALE2};
            *(float4*)(dst + i) = v;
        }
    } else if (EPI == 1) {       // V fp16 + bias
        int r = tid >> 1, ch = tid & 1;
        const float* sp = stg + (size_t)r * 130 + ch * 64;
        float bi = bias[m0 + r];
        __half* dst = (__half*)Cv + (size_t)z * CH * Ss + (size_t)(m0 + r) * Ss + j0 + ch * 64;
#pragma unroll
        for (int i = 0; i < 64; i += 8) {
            uint4 o;
            o.x = packh2(sp[i + 0] + bi, sp[i + 1] + bi);
            o.y = packh2(sp[i + 2] + bi, sp[i + 3] + bi);
            o.z = packh2(sp[i + 4] + bi, sp[i + 5] + bi);
            o.w = packh2(sp[i + 6] + bi, sp[i + 7] + bi);
            *(uint4*)(dst + i) = o;
        }
    } else if (EPI == 2) {       // Q/K fp16 transposed + bias -> [(z*8+h)][s][c]
        int j = tid >> 1, mh = (tid & 1) * 64;
        int s = j0 + j;
        int h = m0 >> 9;
        int c0 = (m0 & 511) + mh;
        __half* dst = (__half*)Cv + (((size_t)(z * 8 + h) * Ss + s) * Cc) + c0;
#pragma unroll
        for (int i = 0; i < 64; i += 8) {
            uint4 o;
            o.x = packh2(stg[(size_t)(mh + i + 0) * 130 + j] + bias[m0 + mh + i + 0],
                         stg[(size_t)(mh + i + 1) * 130 + j] + bias[m0 + mh + i + 1]);
            o.y = packh2(stg[(size_t)(mh + i + 2) * 130 + j] + bias[m0 + mh + i + 2],
                         stg[(size_t)(mh + i + 3) * 130 + j] + bias[m0 + mh + i + 3]);
            o.z = packh2(stg[(size_t)(mh + i + 4) * 130 + j] + bias[m0 + mh + i + 4],
                         stg[(size_t)(mh + i + 5) * 130 + j] + bias[m0 + mh + i + 5]);
            o.w = packh2(stg[(size_t)(mh + i + 6) * 130 + j] + bias[m0 + mh + i + 6],
                         stg[(size_t)(mh + i + 7) * 130 + j] + bias[m0 + mh + i + 7]);
            *(uint4*)(dst + i) = o;
        }
    } else if (EPI == 3) {       // y fp16 transposed -> [n][s][h*512 + m]
        int j = tid >> 1, mh = (tid & 1) * 64;
        int s = j0 + j;
        __half* dst = (__half*)Cv
            + (size_t)(z >> 3) * Ss * CH + (size_t)s * CH + (z & 7) * 512 + m0 + mh;
#pragma unroll
        for (int i = 0; i < 64; i += 8) {
            uint4 o;
            o.x = packh2(stg[(size_t)(mh + i + 0) * 130 + j], stg[(size_t)(mh + i + 1) * 130 + j]);
            o.y = packh2(stg[(size_t)(mh + i + 2) * 130 + j], stg[(size_t)(mh + i + 3) * 130 + j]);
            o.z = packh2(stg[(size_t)(mh + i + 4) * 130 + j], stg[(size_t)(mh + i + 5) * 130 + j]);
            o.w = packh2(stg[(size_t)(mh + i + 6) * 130 + j], stg[(size_t)(mh + i + 7) * 130 + j]);
            *(uint4*)(dst + i) = o;
        }
    } else {                     // EPI 4: out fp32 + bias + residual
        int r = tid >> 1, ch = tid & 1;
        const float* sp = stg + (size_t)r * 130 + ch * 64;
        float bi = bias[m0 + r];
        size_t off = (size_t)z * Cc * Ss + (size_t)(m0 + r) * Ss + j0 + ch * 64;
        float* dst = (float*)Cv + off;
        const float* R = resid + off;
#pragma unroll
        for (int i = 0; i < 64; i += 4) {
            float4 rr = *(const float4*)(R + i);
            float4 v = {sp[i] + bi + rr.x, sp[i + 1] + bi + rr.y,
                        sp[i + 2] + bi + rr.z, sp[i + 3] + bi + rr.w};
            *(float4*)(dst + i) = v;
        }
    }
}

// ===========================================================================
// Softmax: fp32 scores -> fp16 probs, one block per row of 2048
// ===========================================================================
__global__ __launch_bounds__(256) void softmax_kernel() {
    const float* p = g_att + (size_t)blockIdx.x * Ss;
    __half* q = g_attp + (size_t)blockIdx.x * Ss;
    int t = threadIdx.x;
    float v[8];
    float mx = -1e30f;
#pragma unroll
    for (int i = 0; i < 8; i++) { v[i] = p[t + i * 256]; mx = fmaxf(mx, v[i]); }
    __shared__ float sh[256];
    sh[t] = mx; __syncthreads();
    for (int o = 128; o > 0; o >>= 1) {
        if (t < o) sh[t] = fmaxf(sh[t], sh[t + o]);
        __syncthreads();
    }
    mx = sh[0];
    __syncthreads();
    float s = 0.f;
#pragma unroll
    for (int i = 0; i < 8; i++) { v[i] = __expf(v[i] - mx); s += v[i]; }
    sh[t] = s; __syncthreads();
    for (int o = 128; o > 0; o >>= 1) {
        if (t < o) sh[t] += sh[t + o];
        __syncthreads();
    }
    float inv = 1.0f / sh[0];
#pragma unroll
    for (int i = 0; i < 8; i++) q[t + i * 256] = __float2half_rn(v[i] * inv);
}

// ===========================================================================
// Host
// ===========================================================================
extern "C" void kernel_launch(void* const* d_in, const int* in_sizes, int n_in,
                              void* d_out, int out_size) {
    const float* input   = (const float*)d_in[0];
    const float* context = (const float*)d_in[1];
    const float* gamma   = (const float*)d_in[2];
    const float* beta    = (const float*)d_in[3];
    const float* Wq      = (const float*)d_in[4];
    const float* bq      = (const float*)d_in[5];
    const float* Wkv     = (const float*)d_in[6];
    const float* bkv     = (const float*)d_in[7];
    const float* Wo      = (const float*)d_in[8];
    const float* bo      = (const float*)d_in[9];
    float* out = (float*)d_out;

    static int configured = 0;
    if (!configured) {
        cudaFuncSetAttribute(hgemm<0>, cudaFuncAttributeMaxDynamicSharedMemorySize, GEMM_SMEM);
        cudaFuncSetAttribute(hgemm<1>, cudaFuncAttributeMaxDynamicSharedMemorySize, GEMM_SMEM);
        cudaFuncSetAttribute(hgemm<2>, cudaFuncAttributeMaxDynamicSharedMemorySize, GEMM_SMEM);
        cudaFuncSetAttribute(hgemm<3>, cudaFuncAttributeMaxDynamicSharedMemorySize, GEMM_SMEM);
        cudaFuncSetAttribute(hgemm<4>, cudaFuncAttributeMaxDynamicSharedMemorySize, GEMM_SMEM);
        configured = 1;
    }

    __half *wq_h, *wkv_h, *wo_h, *xnT, *ctxT, *qT, *kT, *vb, *attp, *yT;
    float *att;
    cudaGetSymbolAddress((void**)&wq_h,  g_wq);
    cudaGetSymbolAddress((void**)&wkv_h, g_wkv);
    cudaGetSymbolAddress((void**)&wo_h,  g_wo);
    cudaGetSymbolAddress((void**)&xnT,   g_xnT);
    cudaGetSymbolAddress((void**)&ctxT,  g_ctxT);
    cudaGetSymbolAddress((void**)&qT,    g_qT);
    cudaGetSymbolAddress((void**)&kT,    g_kT);
    cudaGetSymbolAddress((void**)&vb,    g_vb);
    cudaGetSymbolAddress((void**)&att,   g_att);
    cudaGetSymbolAddress((void**)&attp,  g_attp);
    cudaGetSymbolAddress((void**)&yT,    g_yT);

    // LayerNorm stats
    ln_part_kernel<<<dim3(128, Nn), 256>>>(input);
    ln_fin_kernel<<<Nn, 128>>>();

    // Weight conversions fp32 -> fp16
    f2h_kernel<<<2048, 256>>>(Wq,  wq_h,  (CH * Cc) / 4);
    f2h_kernel<<<4096, 256>>>(Wkv, wkv_h, (2 * CH * CTXD) / 4);
    f2h_kernel<<<2048, 256>>>(Wo,  wo_h,  (Cc * CH) / 4);

    // LN(input) transposed -> xnT [n][s][c]; context transposed -> ctxT [n][s][d]
    prepT_kernel<true> <<<dim3(Ss / 32, Cc / 32, Nn), dim3(32, 8)>>>(input, xnT, gamma, beta, Cc, Ss);
    prepT_kernel<false><<<dim3(Ss / 32, CTXD / 32, Nn), dim3(32, 8)>>>(context, ctxT, nullptr, nullptr, CTXD, Ss);

    // Q = Wq @ xn + bq  -> qT [n][h][s][c]
    hgemm<2><<<dim3(Ss / 128, CH / 128, Nn), 256, GEMM_SMEM>>>(
        wq_h, Cc, 0, xnT, Cc, (size_t)Ss * Cc, qT, bq, nullptr, Cc / 32);

    // K = Wkv[0:4096] @ ctx + bkv[0:4096] -> kT [n][h][s][c]
    hgemm<2><<<dim3(Ss / 128, CH / 128, Nn), 256, GEMM_SMEM>>>(
        wkv_h, CTXD, 0, ctxT, CTXD, (size_t)Ss * CTXD, kT, bkv, nullptr, CTXD / 32);

    // V = Wkv[4096:8192] @ ctx + bkv[4096:] -> vb [n][o][s]
    hgemm<1><<<dim3(Ss / 128, CH / 128, Nn), 256, GEMM_SMEM>>>(
        wkv_h + (size_t)CH * CTXD, CTXD, 0, ctxT, CTXD, (size_t)Ss * CTXD,
        vb, bkv + CH, nullptr, CTXD / 32);

    // scores = SCALE2 * qT @ kT^T  (per z = n*8+h) -> att fp32
    hgemm<0><<<dim3(Ss / 128, Ss / 128, Nn * Hh), 256, GEMM_SMEM>>>(
        qT, Cc, (size_t)Ss * Cc, kT, Cc, (size_t)Ss * Cc, att, nullptr, nullptr, Cc / 32);

    softmax_kernel<<<Nn * Hh * Ss, 256>>>();

    // y = v @ att^T (per z) -> yT [n][s][o]
    hgemm<3><<<dim3(Ss / 128, Cc / 128, Nn * Hh), 256, GEMM_SMEM>>>(
        vb, Ss, (size_t)Cc * Ss, attp, Ss, (size_t)Ss * Ss, yT, nullptr, nullptr, Ss / 32);

    // out = Wo @ y + bo + input
    hgemm<4><<<dim3(Ss / 128, Cc / 128, Nn), 256, GEMM_SMEM>>>(
        wo_h, CH, 0, yT, CH, (size_t)Ss * CH, out, bo, input, CH / 32);
}

// round 5
// speedup vs baseline: 5.3588x; 1.1229x over previous
#include <cuda_runtime.h>
#include <cuda_fp16.h>
#include <cstdint>

// ===========================================================================
// Problem constants
// ===========================================================================
#define Nn   4
#define Cc   512
#define Ss   2048
#define Hh   8
#define CH   4096    // C*H
#define CTXD 512
#define ZTOT (Nn * Hh * Ss)   // 65536 attention rows

#define SCALE2 0.044194173824159216f   // 512^-0.5
#define LNEPS  1e-5f

// ===========================================================================
// PTX helpers (plain sm_103-compatible: mma.sync / ldmatrix / cp.async)
// ===========================================================================
__device__ __forceinline__ uint32_t smem_to_u32(const void* smem_ptr) {
    uint32_t addr;
    asm("{ .reg .u64 tmp; cvta.to.shared.u64 tmp, %1; cvt.u32.u64 %0, tmp; }"
        : "=r"(addr) : "l"(smem_ptr));
    return addr;
}

__device__ __forceinline__ void cpa16(uint32_t s, const void* g) {
    asm volatile("cp.async.cg.shared.global [%0], [%1], 16;" :: "r"(s), "l"(g));
}
#define CP_COMMIT() asm volatile("cp.async.commit_group;" ::: "memory")
#define CP_WAIT(n)  asm volatile("cp.async.wait_group %0;" :: "n"(n) : "memory")

__device__ __forceinline__ void ldm_x4(uint32_t* r, uint32_t saddr) {
    asm volatile("ldmatrix.sync.aligned.m8n8.x4.shared.b16 {%0,%1,%2,%3}, [%4];"
        : "=r"(r[0]), "=r"(r[1]), "=r"(r[2]), "=r"(r[3]) : "r"(saddr));
}

__device__ __forceinline__ void mma16816(float* c, const uint32_t* a,
                                         uint32_t b0, uint32_t b1) {
    asm volatile(
        "mma.sync.aligned.m16n8k16.row.col.f32.f16.f16.f32 "
        "{%0,%1,%2,%3},{%4,%5,%6,%7},{%8,%9},{%0,%1,%2,%3};"
        : "+f"(c[0]), "+f"(c[1]), "+f"(c[2]), "+f"(c[3])
        : "r"(a[0]), "r"(a[1]), "r"(a[2]), "r"(a[3]), "r"(b0), "r"(b1));
}

__device__ __forceinline__ uint32_t packh2(float a, float b) {
    __half2 h = __floats2half2_rn(a, b);
    return *(uint32_t*)&h;
}

// ===========================================================================
// Scratch (device globals — allocation-free rule)
// ===========================================================================
__device__ __half g_wq [(size_t)CH * Cc];
__device__ __half g_wkv[(size_t)2 * CH * CTXD];
__device__ __half g_wo [(size_t)Cc * CH];
__device__ __half g_xnT [(size_t)Nn * Ss * Cc];      // [n][s][c]
__device__ __half g_ctxT[(size_t)Nn * Ss * CTXD];    // [n][s][d]
__device__ __half g_qT [(size_t)Nn * Hh * Ss * Cc];  // [n][h][s][c]
__device__ __half g_kT [(size_t)Nn * Hh * Ss * Cc];
__device__ __half g_vb [(size_t)Nn * CH * Ss];       // [n][o][s]
__device__ __half g_attp[(size_t)Nn * Hh * Ss * Ss]; // exp(scores), unnormalized
__device__ float  g_rowsum[ZTOT];                    // softmax denominators
__device__ __half g_yT [(size_t)Nn * Ss * CH];       // [n][s][o]
__device__ float g_part[Nn * 128 * 2];
__device__ float g_stats[Nn * 2];

// ===========================================================================
// LayerNorm statistics
// ===========================================================================
__global__ void ln_part_kernel(const float* __restrict__ x) {
    int n = blockIdx.y, b = blockIdx.x;
    const int chunk = (Cc * Ss) / 128;
    const float4* p4 = (const float4*)(x + (size_t)n * Cc * Ss + (size_t)b * chunk);
    float s = 0.f, s2 = 0.f;
    for (int i = threadIdx.x; i < chunk / 4; i += 256) {
        float4 v = p4[i];
        s  += v.x + v.y + v.z + v.w;
        s2 += v.x * v.x + v.y * v.y + v.z * v.z + v.w * v.w;
    }
    __shared__ float sh0[256], sh1[256];
    sh0[threadIdx.x] = s; sh1[threadIdx.x] = s2;
    __syncthreads();
    for (int o = 128; o > 0; o >>= 1) {
        if (threadIdx.x < o) {
            sh0[threadIdx.x] += sh0[threadIdx.x + o];
            sh1[threadIdx.x] += sh1[threadIdx.x + o];
        }
        __syncthreads();
    }
    if (threadIdx.x == 0) {
        g_part[(n * 128 + b) * 2 + 0] = sh0[0];
        g_part[(n * 128 + b) * 2 + 1] = sh1[0];
    }
}

__global__ void ln_fin_kernel() {
    int n = blockIdx.x, t = threadIdx.x;
    float s  = g_part[(n * 128 + t) * 2 + 0];
    float s2 = g_part[(n * 128 + t) * 2 + 1];
    __shared__ float sh0[128], sh1[128];
    sh0[t] = s; sh1[t] = s2;
    __syncthreads();
    for (int o = 64; o > 0; o >>= 1) {
        if (t < o) { sh0[t] += sh0[t + o]; sh1[t] += sh1[t + o]; }
        __syncthreads();
    }
    if (t == 0) {
        const float inv = 1.0f / (float)(Cc * Ss);
        float mu  = sh0[0] * inv;
        float var = sh1[0] * inv - mu * mu;
        g_stats[n * 2 + 0] = mu;
        g_stats[n * 2 + 1] = rsqrtf(var + LNEPS);
    }
}

// Zero the row-sum accumulators (graph replays re-run this each launch)
__global__ void zero_rowsum_kernel() {
    int i = blockIdx.x * 256 + threadIdx.x;     // 64 blocks x 256 = 16384
    ((float4*)g_rowsum)[i] = make_float4(0.f, 0.f, 0.f, 0.f);
}

// ===========================================================================
// Prep: transpose fp32 [z][R][S] -> fp16 [z][S][R], optional LN affine by row
// ===========================================================================
template<bool LN>
__global__ void prepT_kernel(const float* __restrict__ X, __half* __restrict__ O,
                             const float* __restrict__ gamma, const float* __restrict__ beta,
                             int R, int S)
{
    __shared__ float tile[32][33];
    int z = blockIdx.z;
    int s0 = blockIdx.x * 32, r0 = blockIdx.y * 32;
    const float* Xb = X + (size_t)z * R * S;
    __half* Ob = O + (size_t)z * R * S;
    float mu = 0.f, rs = 0.f;
    if (LN) { mu = g_stats[z * 2 + 0]; rs = g_stats[z * 2 + 1]; }
    int tx = threadIdx.x, ty = threadIdx.y;
#pragma unroll
    for (int i = 0; i < 32; i += 8) {
        int r = r0 + ty + i;
        float val = Xb[(size_t)r * S + s0 + tx];
        if (LN) {
            float g = gamma[r] * rs;
            val = val * g + (beta[r] - mu * g);
        }
        tile[ty + i][tx] = val;
    }
    __syncthreads();
#pragma unroll
    for (int i = 0; i < 32; i += 8) {
        int s = s0 + ty + i;
        Ob[(size_t)s * R + r0 + tx] = __float2half_rn(tile[tx][ty + i]);
    }
}

// fp32 -> fp16 elementwise (n4 = elements/4)
__global__ void f2h_kernel(const float* __restrict__ X, __half* __restrict__ O, int n4) {
    int i = blockIdx.x * 256 + threadIdx.x;
    if (i < n4) {
        float4 v = ((const float4*)X)[i];
        __half2* o = (__half2*)O + (size_t)i * 2;
        o[0] = __floats2half2_rn(v.x, v.y);
        o[1] = __floats2half2_rn(v.z, v.w);
    }
}

// ===========================================================================
// fp16 mma.sync GEMM: 128x128 tiles, BK=32, 3-stage cp.async pipeline.
// A: [Mrows][K] K-major fp16.  B: [Nrows][K] K-major fp16.  D = A · B^T (fp32).
// EPI: 0 = exp(scores*SCALE2) fp16 + atomic row sums  (fused softmax phase 1)
//      1 = V fp16 +bias            (C: [z][m][j])
//      2 = Q/K fp16 transposed+bias(C: [(z*8+h)][s][c])
//      3 = y fp16 transposed, / rowsum[q]  (C: [n][s][h*512+m]) (softmax phase 2)
//      4 = out fp32 +bias +residual
// ===========================================================================
#define ROWB   80          // bytes per smem row (32 halfs data + 8 pad)
#define STAGEB 20480       // bytes per pipeline stage
#define GEMM_SMEM 66560    // max(3*20480, 128*130*4)

template<int EPI>
__global__ __launch_bounds__(256, 2) void hgemm(
    const __half* __restrict__ A, size_t lda, size_t aStr,
    const __half* __restrict__ B, size_t ldb, size_t bStr,
    void* __restrict__ Cv,
    const float* __restrict__ bias,
    const float* __restrict__ resid,
    float* __restrict__ rsum,
    int nt)
{
    extern __shared__ __align__(1024) char smem[];
    const uint32_t sb = smem_to_u32(smem);

    const int tid  = threadIdx.x;
    const int warp = tid >> 5;
    const int lane = tid & 31;
    const int wm = warp >> 2;        // 0..1
    const int wn = warp & 3;         // 0..3
    const int z  = blockIdx.z;
    const int m0 = blockIdx.y * 128;
    const int j0 = blockIdx.x * 128;

    const __half* Ab = A + (size_t)z * aStr + (size_t)(m0 + (tid >> 1)) * lda;
    const __half* Bb = B + (size_t)z * bStr + (size_t)(j0 + (tid >> 1)) * ldb;

    const uint32_t srowA = sb + (uint32_t)(tid >> 1) * ROWB + (uint32_t)(tid & 1) * 32;
    const uint32_t srowB = srowA + 10240;
    const int gseg = (tid & 1) * 16;

    auto prefetch = [&](int kt, int buf) {
        uint32_t so = (uint32_t)buf * STAGEB;
        const __half* ga = Ab + (size_t)kt * 32 + gseg;
        const __half* gb = Bb + (size_t)kt * 32 + gseg;
        cpa16(srowA + so,      ga);
        cpa16(srowA + so + 16, ga + 8);
        cpa16(srowB + so,      gb);
        cpa16(srowB + so + 16, gb + 8);
    };

    float acc[4][4][4];
#pragma unroll
    for (int i = 0; i < 4; i++)
#pragma unroll
        for (int j = 0; j < 4; j++)
#pragma unroll
            for (int e = 0; e < 4; e++) acc[i][j][e] = 0.f;

    const int lrow = lane & 15;
    const int lcolb = (lane >> 4) * 16;

    prefetch(0, 0); CP_COMMIT();
    if (nt > 1) prefetch(1, 1);
    CP_COMMIT();

    for (int t = 0; t < nt; t++) {
        if (t + 2 < nt) prefetch(t + 2, (t + 2) % 3);
        CP_COMMIT();
        CP_WAIT(2);
        __syncthreads();

        uint32_t aB = sb + (uint32_t)((t % 3) * STAGEB);
        uint32_t bB = aB + 10240;
#pragma unroll
        for (int ks = 0; ks < 2; ks++) {
            uint32_t colb = (uint32_t)(ks * 32 + lcolb);
            uint32_t a[4][4], bf[2][4];
#pragma unroll
            for (int i = 0; i < 4; i++)
                ldm_x4(a[i], aB + (uint32_t)(wm * 64 + i * 16 + lrow) * ROWB + colb);
#pragma unroll
            for (int p = 0; p < 2; p++)
                ldm_x4(bf[p], bB + (uint32_t)(wn * 32 + p * 16 + lrow) * ROWB + colb);
#pragma unroll
            for (int i = 0; i < 4; i++) {
#pragma unroll
                for (int p = 0; p < 2; p++) {
                    mma16816(acc[i][p * 2 + 0], a[i], bf[p][0], bf[p][2]);
                    mma16816(acc[i][p * 2 + 1], a[i], bf[p][1], bf[p][3]);
                }
            }
        }
        __syncthreads();
    }

    // ---- stage D (fp32) into smem [128][130] ----
    float* stg = (float*)smem;
    {
        int r = lane >> 2, cq = (lane & 3) * 2;
#pragma unroll
        for (int i = 0; i < 4; i++) {
            int row = wm * 64 + i * 16 + r;
#pragma unroll
            for (int j = 0; j < 4; j++) {
                int col = wn * 32 + j * 8 + cq;
                float2 lo = {acc[i][j][0], acc[i][j][1]};
                float2 hi = {acc[i][j][2], acc[i][j][3]};
                *(float2*)&stg[(size_t)row * 130 + col]       = lo;
                *(float2*)&stg[(size_t)(row + 8) * 130 + col] = hi;
            }
        }
    }
    __syncthreads();

    // ---- output phase ----
    if (EPI == 0) {  // exp(scores*SCALE2) -> fp16, accumulate row sums
        int r = tid >> 1, ch = tid & 1;
        const float* sp = stg + (size_t)r * 130 + ch * 64;
        __half* dst = (__half*)Cv + (size_t)z * Ss * Ss + (size_t)(m0 + r) * Ss + j0 + ch * 64;
        float rs = 0.f;
#pragma unroll
        for (int i = 0; i < 64; i += 8) {
            float e0 = __expf(sp[i + 0] * SCALE2), e1 = __expf(sp[i + 1] * SCALE2);
            float e2 = __expf(sp[i + 2] * SCALE2), e3 = __expf(sp[i + 3] * SCALE2);
            float e4 = __expf(sp[i + 4] * SCALE2), e5 = __expf(sp[i + 5] * SCALE2);
            float e6 = __expf(sp[i + 6] * SCALE2), e7 = __expf(sp[i + 7] * SCALE2);
            rs += (e0 + e1 + e2 + e3) + (e4 + e5 + e6 + e7);
            uint4 o;
            o.x = packh2(e0, e1); o.y = packh2(e2, e3);
            o.z = packh2(e4, e5); o.w = packh2(e6, e7);
            *(uint4*)(dst + i) = o;
        }
        atomicAdd(rsum + (size_t)z * Ss + m0 + r, rs);
    } else if (EPI == 1) {       // V fp16 + bias
        int r = tid >> 1, ch = tid & 1;
        const float* sp = stg + (size_t)r * 130 + ch * 64;
        float bi = bias[m0 + r];
        __half* dst = (__half*)Cv + (size_t)z * CH * Ss + (size_t)(m0 + r) * Ss + j0 + ch * 64;
#pragma unroll
        for (int i = 0; i < 64; i += 8) {
            uint4 o;
            o.x = packh2(sp[i + 0] + bi, sp[i + 1] + bi);
            o.y = packh2(sp[i + 2] + bi, sp[i + 3] + bi);
            o.z = packh2(sp[i + 4] + bi, sp[i + 5] + bi);
            o.w = packh2(sp[i + 6] + bi, sp[i + 7] + bi);
            *(uint4*)(dst + i) = o;
        }
    } else if (EPI == 2) {       // Q/K fp16 transposed + bias -> [(z*8+h)][s][c]
        int j = tid >> 1, mh = (tid & 1) * 64;
        int s = j0 + j;
        int h = m0 >> 9;
        int c0 = (m0 & 511) + mh;
        __half* dst = (__half*)Cv + (((size_t)(z * 8 + h) * Ss + s) * Cc) + c0;
#pragma unroll
        for (int i = 0; i < 64; i += 8) {
            uint4 o;
            o.x = packh2(stg[(size_t)(mh + i + 0) * 130 + j] + bias[m0 + mh + i + 0],
                         stg[(size_t)(mh + i + 1) * 130 + j] + bias[m0 + mh + i + 1]);
            o.y = packh2(stg[(size_t)(mh + i + 2) * 130 + j] + bias[m0 + mh + i + 2],
                         stg[(size_t)(mh + i + 3) * 130 + j] + bias[m0 + mh + i + 3]);
            o.z = packh2(stg[(size_t)(mh + i + 4) * 130 + j] + bias[m0 + mh + i + 4],
                         stg[(size_t)(mh + i + 5) * 130 + j] + bias[m0 + mh + i + 5]);
            o.w = packh2(stg[(size_t)(mh + i + 6) * 130 + j] + bias[m0 + mh + i + 6],
                         stg[(size_t)(mh + i + 7) * 130 + j] + bias[m0 + mh + i + 7]);
            *(uint4*)(dst + i) = o;
        }
    } else if (EPI == 3) {       // y fp16 transposed / rowsum -> [n][s][h*512 + m]
        int j = tid >> 1, mh = (tid & 1) * 64;
        int s = j0 + j;
        float inv = 1.0f / rsum[(size_t)z * Ss + j0 + j];
        __half* dst = (__half*)Cv
            + (size_t)(z >> 3) * Ss * CH + (size_t)s * CH + (z & 7) * 512 + m0 + mh;
#pragma unroll
        for (int i = 0; i < 64; i += 8) {
            uint4 o;
            o.x = packh2(stg[(size_t)(mh + i + 0) * 130 + j] * inv,
                         stg[(size_t)(mh + i + 1) * 130 + j] * inv);
            o.y = packh2(stg[(size_t)(mh + i + 2) * 130 + j] * inv,
                         stg[(size_t)(mh + i + 3) * 130 + j] * inv);
            o.z = packh2(stg[(size_t)(mh + i + 4) * 130 + j] * inv,
                         stg[(size_t)(mh + i + 5) * 130 + j] * inv);
            o.w = packh2(stg[(size_t)(mh + i + 6) * 130 + j] * inv,
                         stg[(size_t)(mh + i + 7) * 130 + j] * inv);
            *(uint4*)(dst + i) = o;
        }
    } else {                     // EPI 4: out fp32 + bias + residual
        int r = tid >> 1, ch = tid & 1;
        const float* sp = stg + (size_t)r * 130 + ch * 64;
        float bi = bias[m0 + r];
        size_t off = (size_t)z * Cc * Ss + (size_t)(m0 + r) * Ss + j0 + ch * 64;
        float* dst = (float*)Cv + off;
        const float* R = resid + off;
#pragma unroll
        for (int i = 0; i < 64; i += 4) {
            float4 rr = *(const float4*)(R + i);
            float4 v = {sp[i] + bi + rr.x, sp[i + 1] + bi + rr.y,
                        sp[i + 2] + bi + rr.z, sp[i + 3] + bi + rr.w};
            *(float4*)(dst + i) = v;
        }
    }
}

// ===========================================================================
// Host
// ===========================================================================
extern "C" void kernel_launch(void* const* d_in, const int* in_sizes, int n_in,
                              void* d_out, int out_size) {
    const float* input   = (const float*)d_in[0];
    const float* context = (const float*)d_in[1];
    const float* gamma   = (const float*)d_in[2];
    const float* beta    = (const float*)d_in[3];
    const float* Wq      = (const float*)d_in[4];
    const float* bq      = (const float*)d_in[5];
    const float* Wkv     = (const float*)d_in[6];
    const float* bkv     = (const float*)d_in[7];
    const float* Wo      = (const float*)d_in[8];
    const float* bo      = (const float*)d_in[9];
    float* out = (float*)d_out;

    static int configured = 0;
    if (!configured) {
        cudaFuncSetAttribute(hgemm<0>, cudaFuncAttributeMaxDynamicSharedMemorySize, GEMM_SMEM);
        cudaFuncSetAttribute(hgemm<1>, cudaFuncAttributeMaxDynamicSharedMemorySize, GEMM_SMEM);
        cudaFuncSetAttribute(hgemm<2>, cudaFuncAttributeMaxDynamicSharedMemorySize, GEMM_SMEM);
        cudaFuncSetAttribute(hgemm<3>, cudaFuncAttributeMaxDynamicSharedMemorySize, GEMM_SMEM);
        cudaFuncSetAttribute(hgemm<4>, cudaFuncAttributeMaxDynamicSharedMemorySize, GEMM_SMEM);
        configured = 1;
    }

    __half *wq_h, *wkv_h, *wo_h, *xnT, *ctxT, *qT, *kT, *vb, *attp, *yT;
    float *rsum;
    cudaGetSymbolAddress((void**)&wq_h,  g_wq);
    cudaGetSymbolAddress((void**)&wkv_h, g_wkv);
    cudaGetSymbolAddress((void**)&wo_h,  g_wo);
    cudaGetSymbolAddress((void**)&xnT,   g_xnT);
    cudaGetSymbolAddress((void**)&ctxT,  g_ctxT);
    cudaGetSymbolAddress((void**)&qT,    g_qT);
    cudaGetSymbolAddress((void**)&kT,    g_kT);
    cudaGetSymbolAddress((void**)&vb,    g_vb);
    cudaGetSymbolAddress((void**)&attp,  g_attp);
    cudaGetSymbolAddress((void**)&rsum,  g_rowsum);
    cudaGetSymbolAddress((void**)&yT,    g_yT);

    // LayerNorm stats + rowsum zeroing
    ln_part_kernel<<<dim3(128, Nn), 256>>>(input);
    ln_fin_kernel<<<Nn, 128>>>();
    zero_rowsum_kernel<<<64, 256>>>();

    // Weight conversions fp32 -> fp16
    f2h_kernel<<<2048, 256>>>(Wq,  wq_h,  (CH * Cc) / 4);
    f2h_kernel<<<4096, 256>>>(Wkv, wkv_h, (2 * CH * CTXD) / 4);
    f2h_kernel<<<2048, 256>>>(Wo,  wo_h,  (Cc * CH) / 4);

    // LN(input) transposed -> xnT [n][s][c]; context transposed -> ctxT [n][s][d]
    prepT_kernel<true> <<<dim3(Ss / 32, Cc / 32, Nn), dim3(32, 8)>>>(input, xnT, gamma, beta, Cc, Ss);
    prepT_kernel<false><<<dim3(Ss / 32, CTXD / 32, Nn), dim3(32, 8)>>>(context, ctxT, nullptr, nullptr, CTXD, Ss);

    // Q = Wq @ xn + bq  -> qT [n][h][s][c]
    hgemm<2><<<dim3(Ss / 128, CH / 128, Nn), 256, GEMM_SMEM>>>(
        wq_h, Cc, 0, xnT, Cc, (size_t)Ss * Cc, qT, bq, nullptr, nullptr, Cc / 32);

    // K = Wkv[0:4096] @ ctx + bkv[0:4096] -> kT [n][h][s][c]
    hgemm<2><<<dim3(Ss / 128, CH / 128, Nn), 256, GEMM_SMEM>>>(
        wkv_h, CTXD, 0, ctxT, CTXD, (size_t)Ss * CTXD, kT, bkv, nullptr, nullptr, CTXD / 32);

    // V = Wkv[4096:8192] @ ctx + bkv[4096:] -> vb [n][o][s]
    hgemm<1><<<dim3(Ss / 128, CH / 128, Nn), 256, GEMM_SMEM>>>(
        wkv_h + (size_t)CH * CTXD, CTXD, 0, ctxT, CTXD, (size_t)Ss * CTXD,
        vb, bkv + CH, nullptr, nullptr, CTXD / 32);

    // exp(scores) fp16 + row sums (fused softmax phase 1)
    hgemm<0><<<dim3(Ss / 128, Ss / 128, Nn * Hh), 256, GEMM_SMEM>>>(
        qT, Cc, (size_t)Ss * Cc, kT, Cc, (size_t)Ss * Cc, attp,
        nullptr, nullptr, rsum, Cc / 32);

    // y = (exp @ v^T) / rowsum (fused softmax phase 2) -> yT [n][s][o]
    hgemm<3><<<dim3(Ss / 128, Cc / 128, Nn * Hh), 256, GEMM_SMEM>>>(
        vb, Ss, (size_t)Cc * Ss, attp, Ss, (size_t)Ss * Ss, yT,
        nullptr, nullptr, rsum, Ss / 32);

    // out = Wo @ y + bo + input
    hgemm<4><<<dim3(Ss / 128, Cc / 128, Nn), 256, GEMM_SMEM>>>(
        wo_h, CH, 0, yT, CH, (size_t)Ss * CH, out, bo, input, nullptr, CH / 32);
}

// round 6
// speedup vs baseline: 5.4054x; 1.0087x over previous
#include <cuda_runtime.h>
#include <cuda_fp16.h>
#include <cstdint>

// ===========================================================================
// Problem constants
// ===========================================================================
#define Nn   4
#define Cc   512
#define Ss   2048
#define Hh   8
#define CH   4096    // C*H
#define CTXD 512
#define ZTOT (Nn * Hh * Ss)

#define SCALE2 0.044194173824159216f   // 512^-0.5
#define LNEPS  1e-5f

// ===========================================================================
// PTX helpers (plain sm_103-compatible: mma.sync / ldmatrix / cp.async)
// ===========================================================================
__device__ __forceinline__ uint32_t smem_to_u32(const void* smem_ptr) {
    uint32_t addr;
    asm("{ .reg .u64 tmp; cvta.to.shared.u64 tmp, %1; cvt.u32.u64 %0, tmp; }"
        : "=r"(addr) : "l"(smem_ptr));
    return addr;
}

__device__ __forceinline__ void cpa16(uint32_t s, const void* g) {
    asm volatile("cp.async.cg.shared.global [%0], [%1], 16;" :: "r"(s), "l"(g));
}
#define CP_COMMIT() asm volatile("cp.async.commit_group;" ::: "memory")
#define CP_WAIT(n)  asm volatile("cp.async.wait_group %0;" :: "n"(n) : "memory")

__device__ __forceinline__ void ldm_x4(uint32_t* r, uint32_t saddr) {
    asm volatile("ldmatrix.sync.aligned.m8n8.x4.shared.b16 {%0,%1,%2,%3}, [%4];"
        : "=r"(r[0]), "=r"(r[1]), "=r"(r[2]), "=r"(r[3]) : "r"(saddr));
}

// fp32-accumulate HMMA
__device__ __forceinline__ void mma16816_f32(float* c, const uint32_t* a,
                                             uint32_t b0, uint32_t b1) {
    asm volatile(
        "mma.sync.aligned.m16n8k16.row.col.f32.f16.f16.f32 "
        "{%0,%1,%2,%3},{%4,%5,%6,%7},{%8,%9},{%0,%1,%2,%3};"
        : "+f"(c[0]), "+f"(c[1]), "+f"(c[2]), "+f"(c[3])
        : "r"(a[0]), "r"(a[1]), "r"(a[2]), "r"(a[3]), "r"(b0), "r"(b1));
}

// fp16-accumulate HMMA (2x rate on the legacy pipe)
__device__ __forceinline__ void mma16816_f16(uint32_t* c, const uint32_t* a,
                                             uint32_t b0, uint32_t b1) {
    asm volatile(
        "mma.sync.aligned.m16n8k16.row.col.f16.f16.f16.f16 "
        "{%0,%1},{%2,%3,%4,%5},{%6,%7},{%0,%1};"
        : "+r"(c[0]), "+r"(c[1])
        : "r"(a[0]), "r"(a[1]), "r"(a[2]), "r"(a[3]), "r"(b0), "r"(b1));
}

__device__ __forceinline__ uint32_t packh2(float a, float b) {
    __half2 h = __floats2half2_rn(a, b);
    return *(uint32_t*)&h;
}

// ===========================================================================
// Scratch (device globals — allocation-free rule)
// ===========================================================================
__device__ __half g_wq [(size_t)CH * Cc];
__device__ __half g_wkv[(size_t)2 * CH * CTXD];
__device__ __half g_wo [(size_t)Cc * CH];
__device__ __half g_xnT [(size_t)Nn * Ss * Cc];      // [n][s][c]
__device__ __half g_ctxT[(size_t)Nn * Ss * CTXD];    // [n][s][d]
__device__ __half g_qT [(size_t)Nn * Hh * Ss * Cc];  // [n][h][s][c]
__device__ __half g_kT [(size_t)Nn * Hh * Ss * Cc];
__device__ __half g_vb [(size_t)Nn * CH * Ss];       // [n][o][s]
__device__ __half g_attp[(size_t)Nn * Hh * Ss * Ss]; // exp(scores), unnormalized
__device__ float  g_rowsum[ZTOT];
__device__ __half g_yT [(size_t)Nn * Ss * CH];       // [n][s][o]
__device__ float g_part[Nn * 128 * 2];
__device__ float g_stats[Nn * 2];

// ===========================================================================
// LayerNorm statistics
// ===========================================================================
__global__ void ln_part_kernel(const float* __restrict__ x) {
    int n = blockIdx.y, b = blockIdx.x;
    const int chunk = (Cc * Ss) / 128;
    const float4* p4 = (const float4*)(x + (size_t)n * Cc * Ss + (size_t)b * chunk);
    float s = 0.f, s2 = 0.f;
    for (int i = threadIdx.x; i < chunk / 4; i += 256) {
        float4 v = p4[i];
        s  += v.x + v.y + v.z + v.w;
        s2 += v.x * v.x + v.y * v.y + v.z * v.z + v.w * v.w;
    }
    __shared__ float sh0[256], sh1[256];
    sh0[threadIdx.x] = s; sh1[threadIdx.x] = s2;
    __syncthreads();
    for (int o = 128; o > 0; o >>= 1) {
        if (threadIdx.x < o) {
            sh0[threadIdx.x] += sh0[threadIdx.x + o];
            sh1[threadIdx.x] += sh1[threadIdx.x + o];
        }
        __syncthreads();
    }
    if (threadIdx.x == 0) {
        g_part[(n * 128 + b) * 2 + 0] = sh0[0];
        g_part[(n * 128 + b) * 2 + 1] = sh1[0];
    }
}

__global__ void ln_fin_kernel() {
    int n = blockIdx.x, t = threadIdx.x;
    float s  = g_part[(n * 128 + t) * 2 + 0];
    float s2 = g_part[(n * 128 + t) * 2 + 1];
    __shared__ float sh0[128], sh1[128];
    sh0[t] = s; sh1[t] = s2;
    __syncthreads();
    for (int o = 64; o > 0; o >>= 1) {
        if (t < o) { sh0[t] += sh0[t + o]; sh1[t] += sh1[t + o]; }
        __syncthreads();
    }
    if (t == 0) {
        const float inv = 1.0f / (float)(Cc * Ss);
        float mu  = sh0[0] * inv;
        float var = sh1[0] * inv - mu * mu;
        g_stats[n * 2 + 0] = mu;
        g_stats[n * 2 + 1] = rsqrtf(var + LNEPS);
    }
}

__global__ void zero_rowsum_kernel() {
    int i = blockIdx.x * 256 + threadIdx.x;
    ((float4*)g_rowsum)[i] = make_float4(0.f, 0.f, 0.f, 0.f);
}

// ===========================================================================
// Prep: transpose fp32 [z][R][S] -> fp16 [z][S][R], optional LN affine by row
// ===========================================================================
template<bool LN>
__global__ void prepT_kernel(const float* __restrict__ X, __half* __restrict__ O,
                             const float* __restrict__ gamma, const float* __restrict__ beta,
                             int R, int S)
{
    __shared__ float tile[32][33];
    int z = blockIdx.z;
    int s0 = blockIdx.x * 32, r0 = blockIdx.y * 32;
    const float* Xb = X + (size_t)z * R * S;
    __half* Ob = O + (size_t)z * R * S;
    float mu = 0.f, rs = 0.f;
    if (LN) { mu = g_stats[z * 2 + 0]; rs = g_stats[z * 2 + 1]; }
    int tx = threadIdx.x, ty = threadIdx.y;
#pragma unroll
    for (int i = 0; i < 32; i += 8) {
        int r = r0 + ty + i;
        float val = Xb[(size_t)r * S + s0 + tx];
        if (LN) {
            float g = gamma[r] * rs;
            val = val * g + (beta[r] - mu * g);
        }
        tile[ty + i][tx] = val;
    }
    __syncthreads();
#pragma unroll
    for (int i = 0; i < 32; i += 8) {
        int s = s0 + ty + i;
        Ob[(size_t)s * R + r0 + tx] = __float2half_rn(tile[tx][ty + i]);
    }
}

__global__ void f2h_kernel(const float* __restrict__ X, __half* __restrict__ O, int n4) {
    int i = blockIdx.x * 256 + threadIdx.x;
    if (i < n4) {
        float4 v = ((const float4*)X)[i];
        __half2* o = (__half2*)O + (size_t)i * 2;
        o[0] = __floats2half2_rn(v.x, v.y);
        o[1] = __floats2half2_rn(v.z, v.w);
    }
}

// ===========================================================================
// fp16 mma.sync GEMM: 128x128 tiles, BK=32, 3-stage cp.async pipeline.
// A: [Mrows][K] K-major fp16.  B: [Nrows][K] K-major fp16.
// H16: use fp16 accumulators (2x HMMA rate); else fp32 accumulators.
// EPI: 0 = exp(scores*SCALE2) fp16 + atomic row sums
//      1 = V fp16 +bias            (C: [z][m][j])
//      2 = Q/K fp16 transposed+bias(C: [(z*8+h)][s][c])
//      3 = y fp16 transposed, / rowsum[q]  (C: [n][s][h*512+m])
//      4 = out fp32 +bias +residual
// ===========================================================================
#define ROWB   80
#define STAGEB 20480
#define GEMM_SMEM 66560

template<int EPI, bool H16>
__global__ __launch_bounds__(256, 2) void hgemm(
    const __half* __restrict__ A, size_t lda, size_t aStr,
    const __half* __restrict__ B, size_t ldb, size_t bStr,
    void* __restrict__ Cv,
    const float* __restrict__ bias,
    const float* __restrict__ resid,
    float* __restrict__ rsum,
    int nt)
{
    extern __shared__ __align__(1024) char smem[];
    const uint32_t sb = smem_to_u32(smem);

    const int tid  = threadIdx.x;
    const int warp = tid >> 5;
    const int lane = tid & 31;
    const int wm = warp >> 2;
    const int wn = warp & 3;
    const int z  = blockIdx.z;
    const int m0 = blockIdx.y * 128;
    const int j0 = blockIdx.x * 128;

    const __half* Ab = A + (size_t)z * aStr + (size_t)(m0 + (tid >> 1)) * lda;
    const __half* Bb = B + (size_t)z * bStr + (size_t)(j0 + (tid >> 1)) * ldb;

    const uint32_t srowA = sb + (uint32_t)(tid >> 1) * ROWB + (uint32_t)(tid & 1) * 32;
    const uint32_t srowB = srowA + 10240;
    const int gseg = (tid & 1) * 16;

    auto prefetch = [&](int kt, int buf) {
        uint32_t so = (uint32_t)buf * STAGEB;
        const __half* ga = Ab + (size_t)kt * 32 + gseg;
        const __half* gb = Bb + (size_t)kt * 32 + gseg;
        cpa16(srowA + so,      ga);
        cpa16(srowA + so + 16, ga + 8);
        cpa16(srowB + so,      gb);
        cpa16(srowB + so + 16, gb + 8);
    };

    float    accf[H16 ? 1 : 4][4][4];
    uint32_t acch[H16 ? 4 : 1][4][2];
    if (H16) {
#pragma unroll
        for (int i = 0; i < (H16 ? 4 : 1); i++)
#pragma unroll
            for (int j = 0; j < 4; j++) { acch[i][j][0] = 0u; acch[i][j][1] = 0u; }
    } else {
#pragma unroll
        for (int i = 0; i < (H16 ? 1 : 4); i++)
#pragma unroll
            for (int j = 0; j < 4; j++)
#pragma unroll
                for (int e = 0; e < 4; e++) accf[i][j][e] = 0.f;
    }

    const int lrow = lane & 15;
    const int lcolb = (lane >> 4) * 16;

    prefetch(0, 0); CP_COMMIT();
    if (nt > 1) prefetch(1, 1);
    CP_COMMIT();

    for (int t = 0; t < nt; t++) {
        if (t + 2 < nt) prefetch(t + 2, (t + 2) % 3);
        CP_COMMIT();
        CP_WAIT(2);
        __syncthreads();

        uint32_t aB = sb + (uint32_t)((t % 3) * STAGEB);
        uint32_t bB = aB + 10240;
#pragma unroll
        for (int ks = 0; ks < 2; ks++) {
            uint32_t colb = (uint32_t)(ks * 32 + lcolb);
            uint32_t a[4][4], bf[2][4];
#pragma unroll
            for (int i = 0; i < 4; i++)
                ldm_x4(a[i], aB + (uint32_t)(wm * 64 + i * 16 + lrow) * ROWB + colb);
#pragma unroll
            for (int p = 0; p < 2; p++)
                ldm_x4(bf[p], bB + (uint32_t)(wn * 32 + p * 16 + lrow) * ROWB + colb);
#pragma unroll
            for (int i = 0; i < 4; i++) {
#pragma unroll
                for (int p = 0; p < 2; p++) {
                    if (H16) {
                        mma16816_f16(acch[i][p * 2 + 0], a[i], bf[p][0], bf[p][2]);
                        mma16816_f16(acch[i][p * 2 + 1], a[i], bf[p][1], bf[p][3]);
                    } else {
                        mma16816_f32(accf[i][p * 2 + 0], a[i], bf[p][0], bf[p][2]);
                        mma16816_f32(accf[i][p * 2 + 1], a[i], bf[p][1], bf[p][3]);
                    }
                }
            }
        }
        __syncthreads();
    }

    // ---- stage D (fp32) into smem [128][130] ----
    float* stg = (float*)smem;
    {
        int r = lane >> 2, cq = (lane & 3) * 2;
#pragma unroll
        for (int i = 0; i < 4; i++) {
            int row = wm * 64 + i * 16 + r;
#pragma unroll
            for (int j = 0; j < 4; j++) {
                int col = wn * 32 + j * 8 + cq;
                float2 lo, hi;
                if (H16) {
                    lo = __half22float2(*(const __half2*)&acch[i][j][0]);
                    hi = __half22float2(*(const __half2*)&acch[i][j][1]);
                } else {
                    lo = make_float2(accf[i][j][0], accf[i][j][1]);
                    hi = make_float2(accf[i][j][2], accf[i][j][3]);
                }
                *(float2*)&stg[(size_t)row * 130 + col]       = lo;
                *(float2*)&stg[(size_t)(row + 8) * 130 + col] = hi;
            }
        }
    }
    __syncthreads();

    // ---- output phase ----
    if (EPI == 0) {  // exp(scores*SCALE2) -> fp16, accumulate row sums
        int r = tid >> 1, ch = tid & 1;
        const float* sp = stg + (size_t)r * 130 + ch * 64;
        __half* dst = (__half*)Cv + (size_t)z * Ss * Ss + (size_t)(m0 + r) * Ss + j0 + ch * 64;
        float rs = 0.f;
#pragma unroll
        for (int i = 0; i < 64; i += 8) {
            float e0 = __expf(sp[i + 0] * SCALE2), e1 = __expf(sp[i + 1] * SCALE2);
            float e2 = __expf(sp[i + 2] * SCALE2), e3 = __expf(sp[i + 3] * SCALE2);
            float e4 = __expf(sp[i + 4] * SCALE2), e5 = __expf(sp[i + 5] * SCALE2);
            float e6 = __expf(sp[i + 6] * SCALE2), e7 = __expf(sp[i + 7] * SCALE2);
            rs += (e0 + e1 + e2 + e3) + (e4 + e5 + e6 + e7);
            uint4 o;
            o.x = packh2(e0, e1); o.y = packh2(e2, e3);
            o.z = packh2(e4, e5); o.w = packh2(e6, e7);
            *(uint4*)(dst + i) = o;
        }
        atomicAdd(rsum + (size_t)z * Ss + m0 + r, rs);
    } else if (EPI == 1) {       // V fp16 + bias
        int r = tid >> 1, ch = tid & 1;
        const float* sp = stg + (size_t)r * 130 + ch * 64;
        float bi = bias[m0 + r];
        __half* dst = (__half*)Cv + (size_t)z * CH * Ss + (size_t)(m0 + r) * Ss + j0 + ch * 64;
#pragma unroll
        for (int i = 0; i < 64; i += 8) {
            uint4 o;
            o.x = packh2(sp[i + 0] + bi, sp[i + 1] + bi);
            o.y = packh2(sp[i + 2] + bi, sp[i + 3] + bi);
            o.z = packh2(sp[i + 4] + bi, sp[i + 5] + bi);
            o.w = packh2(sp[i + 6] + bi, sp[i + 7] + bi);
            *(uint4*)(dst + i) = o;
        }
    } else if (EPI == 2) {       // Q/K fp16 transposed + bias -> [(z*8+h)][s][c]
        int j = tid >> 1, mh = (tid & 1) * 64;
        int s = j0 + j;
        int h = m0 >> 9;
        int c0 = (m0 & 511) + mh;
        __half* dst = (__half*)Cv + (((size_t)(z * 8 + h) * Ss + s) * Cc) + c0;
#pragma unroll
        for (int i = 0; i < 64; i += 8) {
            uint4 o;
            o.x = packh2(stg[(size_t)(mh + i + 0) * 130 + j] + bias[m0 + mh + i + 0],
                         stg[(size_t)(mh + i + 1) * 130 + j] + bias[m0 + mh + i + 1]);
            o.y = packh2(stg[(size_t)(mh + i + 2) * 130 + j] + bias[m0 + mh + i + 2],
                         stg[(size_t)(mh + i + 3) * 130 + j] + bias[m0 + mh + i + 3]);
            o.z = packh2(stg[(size_t)(mh + i + 4) * 130 + j] + bias[m0 + mh + i + 4],
                         stg[(size_t)(mh + i + 5) * 130 + j] + bias[m0 + mh + i + 5]);
            o.w = packh2(stg[(size_t)(mh + i + 6) * 130 + j] + bias[m0 + mh + i + 6],
                         stg[(size_t)(mh + i + 7) * 130 + j] + bias[m0 + mh + i + 7]);
            *(uint4*)(dst + i) = o;
        }
    } else if (EPI == 3) {       // y fp16 transposed / rowsum -> [n][s][h*512 + m]
        int j = tid >> 1, mh = (tid & 1) * 64;
        int s = j0 + j;
        float inv = 1.0f / rsum[(size_t)z * Ss + j0 + j];
        __half* dst = (__half*)Cv
            + (size_t)(z >> 3) * Ss * CH + (size_t)s * CH + (z & 7) * 512 + m0 + mh;
#pragma unroll
        for (int i = 0; i < 64; i += 8) {
            uint4 o;
            o.x = packh2(stg[(size_t)(mh + i + 0) * 130 + j] * inv,
                         stg[(size_t)(mh + i + 1) * 130 + j] * inv);
            o.y = packh2(stg[(size_t)(mh + i + 2) * 130 + j] * inv,
                         stg[(size_t)(mh + i + 3) * 130 + j] * inv);
            o.z = packh2(stg[(size_t)(mh + i + 4) * 130 + j] * inv,
                         stg[(size_t)(mh + i + 5) * 130 + j] * inv);
            o.w = packh2(stg[(size_t)(mh + i + 6) * 130 + j] * inv,
                         stg[(size_t)(mh + i + 7) * 130 + j] * inv);
            *(uint4*)(dst + i) = o;
        }
    } else {                     // EPI 4: out fp32 + bias + residual
        int r = tid >> 1, ch = tid & 1;
        const float* sp = stg + (size_t)r * 130 + ch * 64;
        float bi = bias[m0 + r];
        size_t off = (size_t)z * Cc * Ss + (size_t)(m0 + r) * Ss + j0 + ch * 64;
        float* dst = (float*)Cv + off;
        const float* R = resid + off;
#pragma unroll
        for (int i = 0; i < 64; i += 4) {
            float4 rr = *(const float4*)(R + i);
            float4 v = {sp[i] + bi + rr.x, sp[i + 1] + bi + rr.y,
                        sp[i + 2] + bi + rr.z, sp[i + 3] + bi + rr.w};
            *(float4*)(dst + i) = v;
        }
    }
}

// ===========================================================================
// Host
// ===========================================================================
extern "C" void kernel_launch(void* const* d_in, const int* in_sizes, int n_in,
                              void* d_out, int out_size) {
    const float* input   = (const float*)d_in[0];
    const float* context = (const float*)d_in[1];
    const float* gamma   = (const float*)d_in[2];
    const float* beta    = (const float*)d_in[3];
    const float* Wq      = (const float*)d_in[4];
    const float* bq      = (const float*)d_in[5];
    const float* Wkv     = (const float*)d_in[6];
    const float* bkv     = (const float*)d_in[7];
    const float* Wo      = (const float*)d_in[8];
    const float* bo      = (const float*)d_in[9];
    float* out = (float*)d_out;

    static int configured = 0;
    if (!configured) {
        cudaFuncSetAttribute(hgemm<0, true>,  cudaFuncAttributeMaxDynamicSharedMemorySize, GEMM_SMEM);
        cudaFuncSetAttribute(hgemm<1, true>,  cudaFuncAttributeMaxDynamicSharedMemorySize, GEMM_SMEM);
        cudaFuncSetAttribute(hgemm<2, true>,  cudaFuncAttributeMaxDynamicSharedMemorySize, GEMM_SMEM);
        cudaFuncSetAttribute(hgemm<3, true>,  cudaFuncAttributeMaxDynamicSharedMemorySize, GEMM_SMEM);
        cudaFuncSetAttribute(hgemm<4, false>, cudaFuncAttributeMaxDynamicSharedMemorySize, GEMM_SMEM);
        configured = 1;
    }

    __half *wq_h, *wkv_h, *wo_h, *xnT, *ctxT, *qT, *kT, *vb, *attp, *yT;
    float *rsum;
    cudaGetSymbolAddress((void**)&wq_h,  g_wq);
    cudaGetSymbolAddress((void**)&wkv_h, g_wkv);
    cudaGetSymbolAddress((void**)&wo_h,  g_wo);
    cudaGetSymbolAddress((void**)&xnT,   g_xnT);
    cudaGetSymbolAddress((void**)&ctxT,  g_ctxT);
    cudaGetSymbolAddress((void**)&qT,    g_qT);
    cudaGetSymbolAddress((void**)&kT,    g_kT);
    cudaGetSymbolAddress((void**)&vb,    g_vb);
    cudaGetSymbolAddress((void**)&attp,  g_attp);
    cudaGetSymbolAddress((void**)&rsum,  g_rowsum);
    cudaGetSymbolAddress((void**)&yT,    g_yT);

    ln_part_kernel<<<dim3(128, Nn), 256>>>(input);
    ln_fin_kernel<<<Nn, 128>>>();
    zero_rowsum_kernel<<<64, 256>>>();

    f2h_kernel<<<2048, 256>>>(Wq,  wq_h,  (CH * Cc) / 4);
    f2h_kernel<<<4096, 256>>>(Wkv, wkv_h, (2 * CH * CTXD) / 4);
    f2h_kernel<<<2048, 256>>>(Wo,  wo_h,  (Cc * CH) / 4);

    prepT_kernel<true> <<<dim3(Ss / 32, Cc / 32, Nn), dim3(32, 8)>>>(input, xnT, gamma, beta, Cc, Ss);
    prepT_kernel<false><<<dim3(Ss / 32, CTXD / 32, Nn), dim3(32, 8)>>>(context, ctxT, nullptr, nullptr, CTXD, Ss);

    // Q = Wq @ xn + bq  -> qT [n][h][s][c]     (f16 acc)
    hgemm<2, true><<<dim3(Ss / 128, CH / 128, Nn), 256, GEMM_SMEM>>>(
        wq_h, Cc, 0, xnT, Cc, (size_t)Ss * Cc, qT, bq, nullptr, nullptr, Cc / 32);

    // K = Wkv[0:4096] @ ctx + bkv -> kT        (f16 acc)
    hgemm<2, true><<<dim3(Ss / 128, CH / 128, Nn), 256, GEMM_SMEM>>>(
        wkv_h, CTXD, 0, ctxT, CTXD, (size_t)Ss * CTXD, kT, bkv, nullptr, nullptr, CTXD / 32);

    // V = Wkv[4096:] @ ctx + bkv[4096:] -> vb  (f16 acc)
    hgemm<1, true><<<dim3(Ss / 128, CH / 128, Nn), 256, GEMM_SMEM>>>(
        wkv_h + (size_t)CH * CTXD, CTXD, 0, ctxT, CTXD, (size_t)Ss * CTXD,
        vb, bkv + CH, nullptr, nullptr, CTXD / 32);

    // exp(scores) fp16 + row sums              (f16 acc)
    hgemm<0, true><<<dim3(Ss / 128, Ss / 128, Nn * Hh), 256, GEMM_SMEM>>>(
        qT, Cc, (size_t)Ss * Cc, kT, Cc, (size_t)Ss * Cc, attp,
        nullptr, nullptr, rsum, Cc / 32);

    // y = (exp @ v^T) / rowsum -> yT           (f16 acc)
    hgemm<3, true><<<dim3(Ss / 128, Cc / 128, Nn * Hh), 256, GEMM_SMEM>>>(
        vb, Ss, (size_t)Cc * Ss, attp, Ss, (size_t)Ss * Ss, yT,
        nullptr, nullptr, rsum, Ss / 32);

    // out = Wo @ y + bo + input                (f32 acc, final precision)
    hgemm<4, false><<<dim3(Ss / 128, Cc / 128, Nn), 256, GEMM_SMEM>>>(
        wo_h, CH, 0, yT, CH, (size_t)Ss * CH, out, bo, input, nullptr, CH / 32);
}